// round 5
// baseline (speedup 1.0000x reference)
#include <cuda_runtime.h>
#include <cuda_bf16.h>
#include <cstdint>

#define BH 32
#define Lq 1024
#define Dd 64

// Scratch: hi/lo bf16 split of projected activations.
__device__ __nv_bfloat16 g_Xhi[BH * Lq * Dd];
__device__ __nv_bfloat16 g_Xlo[BH * Lq * Dd];
__device__ __nv_bfloat16 g_Yhi[BH * Lq * Dd];
__device__ __nv_bfloat16 g_Ylo[BH * Lq * Dd];

// ======================== helpers ===========================
__device__ __forceinline__ uint32_t smem_u32(const void* p) {
    uint32_t a;
    asm("{ .reg .u64 t; cvta.to.shared.u64 t, %1; cvt.u32.u64 %0, t; }"
        : "=r"(a) : "l"(p));
    return a;
}
#define CP16(dst, src) \
    asm volatile("cp.async.cg.shared.global [%0], [%1], 16;" :: "r"(dst), "l"(src) : "memory")
#define CP_COMMIT() asm volatile("cp.async.commit_group;" ::: "memory")
#define CP_WAIT(n)  asm volatile("cp.async.wait_group %0;" :: "n"(n) : "memory")

__device__ __forceinline__ void ldm4(uint32_t* r, uint32_t addr) {
    asm volatile("ldmatrix.sync.aligned.m8n8.x4.shared.b16 {%0,%1,%2,%3}, [%4];"
                 : "=r"(r[0]), "=r"(r[1]), "=r"(r[2]), "=r"(r[3]) : "r"(addr));
}
__device__ __forceinline__ void mma_bf16(float* c, const uint32_t* a, const uint32_t* b) {
    asm volatile(
        "mma.sync.aligned.m16n8k16.row.col.f32.bf16.bf16.f32 "
        "{%0,%1,%2,%3}, {%4,%5,%6,%7}, {%8,%9}, {%0,%1,%2,%3};"
        : "+f"(c[0]), "+f"(c[1]), "+f"(c[2]), "+f"(c[3])
        : "r"(a[0]), "r"(a[1]), "r"(a[2]), "r"(a[3]), "r"(b[0]), "r"(b[1]));
}
__device__ __forceinline__ uint32_t pck(__nv_bfloat16 a, __nv_bfloat16 b) {
    __nv_bfloat162 t; t.x = a; t.y = b;
    return *(uint32_t*)&t;
}
__device__ __forceinline__ void split4(float4 v, uint2& h, uint2& l) {
    __nv_bfloat16 h0 = __float2bfloat16(v.x), h1 = __float2bfloat16(v.y);
    __nv_bfloat16 h2 = __float2bfloat16(v.z), h3 = __float2bfloat16(v.w);
    __nv_bfloat16 l0 = __float2bfloat16(v.x - __bfloat162float(h0));
    __nv_bfloat16 l1 = __float2bfloat16(v.y - __bfloat162float(h1));
    __nv_bfloat16 l2 = __float2bfloat16(v.z - __bfloat162float(h2));
    __nv_bfloat16 l3 = __float2bfloat16(v.w - __bfloat162float(h3));
    h.x = pck(h0, h1); h.y = pck(h2, h3);
    l.x = pck(l0, l1); l.y = pck(l2, l3);
}

#define SA 72   // bf16 tile stride (144 B rows)

__device__ __forceinline__ uint32_t fr(const __nv_bfloat16* t, int row, int k) {
    return *(const uint32_t*)(t + row * SA + k);
}

// ---------------------------------------------------------------------------
// Stage 1: projection as HMMA GEMM (unchanged from R4 — it hit its target).
// ---------------------------------------------------------------------------
__global__ __launch_bounds__(256) void stage1_kernel(
    const float* __restrict__ X, const float* __restrict__ Y,
    const float* __restrict__ W1, const float* __restrict__ b1,
    const float* __restrict__ w2)
{
    extern __shared__ __nv_bfloat16 s1[];
    __nv_bfloat16* sXhi = s1;
    __nv_bfloat16* sXlo = s1 + 128 * SA;
    __nv_bfloat16* sWhi = s1 + 2 * 128 * SA;
    __nv_bfloat16* sWlo = sWhi + 64 * SA;
    float* sb1 = (float*)(sWlo + 64 * SA);
    float* sw2 = sb1 + 64;

    const int tid = threadIdx.x;
    const bool isX = (blockIdx.y == 0);
    const float* __restrict__ src = isX ? X : Y;
    __nv_bfloat16* __restrict__ dhi = isX ? g_Xhi : g_Yhi;
    __nv_bfloat16* __restrict__ dlo = isX ? g_Xlo : g_Ylo;
    const int rowBase = blockIdx.x * 128;

    {
        const float4* w4 = (const float4*)W1;
        #pragma unroll
        for (int i = 0; i < 4; ++i) {
            int idx = tid + i * 256;
            int d = idx >> 4, kq = idx & 15;
            uint2 h, l;
            split4(w4[idx], h, l);
            *(uint2*)&sWhi[d * SA + kq * 4] = h;
            *(uint2*)&sWlo[d * SA + kq * 4] = l;
        }
    }
    {
        const float4* x4 = (const float4*)(src + (size_t)rowBase * 64);
        #pragma unroll
        for (int i = 0; i < 8; ++i) {
            int idx = tid + i * 256;
            int r = idx >> 4, kq = idx & 15;
            uint2 h, l;
            split4(x4[idx], h, l);
            *(uint2*)&sXhi[r * SA + kq * 4] = h;
            *(uint2*)&sXlo[r * SA + kq * 4] = l;
        }
    }
    if (tid < 64) { sb1[tid] = b1[tid]; sw2[tid] = w2[tid]; }
    __syncthreads();

    const int wid = tid >> 5, lane = tid & 31;
    const int wm = (wid >> 1) * 32;
    const int wn = (wid & 1) * 32;
    const int g = lane >> 2, tg2 = (lane & 3) * 2;

    float acc[2][4][4];
    #pragma unroll
    for (int mi = 0; mi < 2; ++mi)
        #pragma unroll
        for (int ni = 0; ni < 4; ++ni)
            #pragma unroll
            for (int q = 0; q < 4; ++q) acc[mi][ni][q] = 0.0f;

    #pragma unroll
    for (int ks = 0; ks < 4; ++ks) {
        const int k0 = ks * 16;
        uint32_t a[2][4], bh[4][2], bl[4][2];
        #pragma unroll
        for (int ni = 0; ni < 4; ++ni) {
            int n = wn + ni * 8 + g;
            bh[ni][0] = fr(sWhi, n, k0 + tg2);
            bh[ni][1] = fr(sWhi, n, k0 + tg2 + 8);
            bl[ni][0] = fr(sWlo, n, k0 + tg2);
            bl[ni][1] = fr(sWlo, n, k0 + tg2 + 8);
        }
        #pragma unroll
        for (int mi = 0; mi < 2; ++mi) {
            int r = wm + mi * 16;
            a[mi][0] = fr(sXhi, r + g,     k0 + tg2);
            a[mi][1] = fr(sXhi, r + g + 8, k0 + tg2);
            a[mi][2] = fr(sXhi, r + g,     k0 + tg2 + 8);
            a[mi][3] = fr(sXhi, r + g + 8, k0 + tg2 + 8);
        }
        #pragma unroll
        for (int mi = 0; mi < 2; ++mi)
            #pragma unroll
            for (int ni = 0; ni < 4; ++ni) {
                mma_bf16(acc[mi][ni], a[mi], bh[ni]);
                mma_bf16(acc[mi][ni], a[mi], bl[ni]);
            }
        #pragma unroll
        for (int mi = 0; mi < 2; ++mi) {
            int r = wm + mi * 16;
            a[mi][0] = fr(sXlo, r + g,     k0 + tg2);
            a[mi][1] = fr(sXlo, r + g + 8, k0 + tg2);
            a[mi][2] = fr(sXlo, r + g,     k0 + tg2 + 8);
            a[mi][3] = fr(sXlo, r + g + 8, k0 + tg2 + 8);
        }
        #pragma unroll
        for (int mi = 0; mi < 2; ++mi)
            #pragma unroll
            for (int ni = 0; ni < 4; ++ni)
                mma_bf16(acc[mi][ni], a[mi], bh[ni]);
    }

    #pragma unroll
    for (int mi = 0; mi < 2; ++mi) {
        #pragma unroll
        for (int ni = 0; ni < 4; ++ni) {
            const int col = wn + ni * 8 + tg2;
            float ba = sb1[col], bb = sb1[col + 1];
            float wa = sw2[col], wb = sw2[col + 1];
            const float* c = acc[mi][ni];
            #pragma unroll
            for (int half = 0; half < 2; ++half) {
                int row = rowBase + wm + mi * 16 + g + half * 8;
                float v0 = c[2 * half + 0] + ba;
                float v1 = c[2 * half + 1] + bb;
                if (isX) { v0 *= wa; v1 *= wb; }
                __nv_bfloat16 h0 = __float2bfloat16(v0);
                __nv_bfloat16 h1 = __float2bfloat16(v1);
                __nv_bfloat16 l0 = __float2bfloat16(v0 - __bfloat162float(h0));
                __nv_bfloat16 l1 = __float2bfloat16(v1 - __bfloat162float(h1));
                size_t eoff = (size_t)row * 64 + col;
                *(uint32_t*)(dhi + eoff) = pck(h0, h1);
                *(uint32_t*)(dlo + eoff) = pck(l0, l1);
            }
        }
    }
}

// ---------------------------------------------------------------------------
// Stage 2: HMMA split GEMM, 128x256 strip per CTA, A amortized, B pipelined.
// grid = (8, 4, 32), block = 256, smem = 110592 B (2 CTAs/SM).
// smem: A_hi | A_lo | B0_hi | B0_lo | B1_hi | B1_lo   (18432 B each)
// ---------------------------------------------------------------------------
#define TILE_B 18432u

__global__ __launch_bounds__(256, 2) void stage2_mma(
    const float* __restrict__ b2p, float* __restrict__ out)
{
    extern __shared__ __nv_bfloat16 sm2[];
    const uint32_t sb = smem_u32(sm2);

    const int tid   = threadIdx.x;
    const int bhz   = blockIdx.z;
    const int mBase = blockIdx.x * 128;
    const int nBase = blockIdx.y * 256;

    // ---- prologue fills
    {
        const uint4* aSrc[2] = {
            (const uint4*)(g_Xhi + (size_t)(bhz * Lq + mBase) * 64),
            (const uint4*)(g_Xlo + (size_t)(bhz * Lq + mBase) * 64)};
        #pragma unroll
        for (int t = 0; t < 2; ++t) {
            uint32_t db = sb + t * TILE_B;
            #pragma unroll
            for (int i = 0; i < 4; ++i) {
                int idx = tid + i * 256;
                int row = idx >> 3, c = idx & 7;
                CP16(db + (uint32_t)row * 144 + (uint32_t)c * 16, aSrc[t] + idx);
            }
        }
        // B0
        const uint4* b0Src[2] = {
            (const uint4*)(g_Yhi + (size_t)(bhz * Lq + nBase) * 64),
            (const uint4*)(g_Ylo + (size_t)(bhz * Lq + nBase) * 64)};
        #pragma unroll
        for (int t = 0; t < 2; ++t) {
            uint32_t db = sb + (2 + t) * TILE_B;
            #pragma unroll
            for (int i = 0; i < 4; ++i) {
                int idx = tid + i * 256;
                int row = idx >> 3, c = idx & 7;
                CP16(db + (uint32_t)row * 144 + (uint32_t)c * 16, b0Src[t] + idx);
            }
        }
        CP_COMMIT();
        // B1 (prefetch — covered by tile-0 compute)
        const uint4* b1Src[2] = {
            (const uint4*)(g_Yhi + (size_t)(bhz * Lq + nBase + 128) * 64),
            (const uint4*)(g_Ylo + (size_t)(bhz * Lq + nBase + 128) * 64)};
        #pragma unroll
        for (int t = 0; t < 2; ++t) {
            uint32_t db = sb + (4 + t) * TILE_B;
            #pragma unroll
            for (int i = 0; i < 4; ++i) {
                int idx = tid + i * 256;
                int row = idx >> 3, c = idx & 7;
                CP16(db + (uint32_t)row * 144 + (uint32_t)c * 16, b1Src[t] + idx);
            }
        }
        CP_COMMIT();
    }

    // ---- per-lane ldmatrix base offsets
    const int wid = tid >> 5, lane = tid & 31;
    const int wm = (wid >> 2) * 64;
    const int wn = (wid & 3) * 32;
    const int g = lane >> 2, tg2 = (lane & 3) * 2;

    const uint32_t aoff =
        (uint32_t)(wm + (lane & 7) + ((lane >> 3) & 1) * 8) * 144 +
        (uint32_t)((lane >> 4) * 8) * 2;
    const uint32_t uaAhi = sb + aoff;
    const uint32_t uaAlo = sb + TILE_B + aoff;
    uint32_t boff[2];
    #pragma unroll
    for (int p = 0; p < 2; ++p)
        boff[p] =
            (uint32_t)(wn + p * 16 + (lane & 7) + ((lane >> 4) & 1) * 8) * 144 +
            (uint32_t)(((lane >> 3) & 1) * 8) * 2;
    const float b2 = __ldg(b2p);

    CP_WAIT(1);                 // A + B0 resident
    __syncthreads();

    #pragma unroll
    for (int bt = 0; bt < 2; ++bt) {
        const uint32_t uaBhi0 = sb + (2 + 2 * bt) * TILE_B + boff[0];
        const uint32_t uaBhi1 = sb + (2 + 2 * bt) * TILE_B + boff[1];
        const uint32_t uaBlo0 = sb + (3 + 2 * bt) * TILE_B + boff[0];
        const uint32_t uaBlo1 = sb + (3 + 2 * bt) * TILE_B + boff[1];

        float acc[4][4][4];
        #pragma unroll
        for (int mi = 0; mi < 4; ++mi)
            #pragma unroll
            for (int ni = 0; ni < 4; ++ni)
                #pragma unroll
                for (int q = 0; q < 4; ++q) acc[mi][ni][q] = 0.0f;

        #pragma unroll
        for (int ks = 0; ks < 4; ++ks) {
            const uint32_t kb = (uint32_t)ks * 32;
            uint32_t a[4][4], bhf[2][4], blf[2][4];
            ldm4(bhf[0], uaBhi0 + kb);
            ldm4(bhf[1], uaBhi1 + kb);
            ldm4(blf[0], uaBlo0 + kb);
            ldm4(blf[1], uaBlo1 + kb);
            #pragma unroll
            for (int mi = 0; mi < 4; ++mi) ldm4(a[mi], uaAhi + mi * 2304u + kb);
            #pragma unroll
            for (int mi = 0; mi < 4; ++mi)
                #pragma unroll
                for (int ni = 0; ni < 4; ++ni) {
                    mma_bf16(acc[mi][ni], a[mi], &bhf[ni >> 1][(ni & 1) * 2]);
                    mma_bf16(acc[mi][ni], a[mi], &blf[ni >> 1][(ni & 1) * 2]);
                }
            #pragma unroll
            for (int mi = 0; mi < 4; ++mi) ldm4(a[mi], uaAlo + mi * 2304u + kb);
            #pragma unroll
            for (int mi = 0; mi < 4; ++mi)
                #pragma unroll
                for (int ni = 0; ni < 4; ++ni)
                    mma_bf16(acc[mi][ni], a[mi], &bhf[ni >> 1][(ni & 1) * 2]);
        }

        if (bt == 0) {          // B1 arrival barrier overlaps tile-0 epilogue
            CP_WAIT(0);
            __syncthreads();
        }

        // epilogue tile bt
        #pragma unroll
        for (int mi = 0; mi < 4; ++mi) {
            #pragma unroll
            for (int ni = 0; ni < 4; ++ni) {
                int r = mBase + wm + mi * 16 + g;
                int c = nBase + bt * 128 + wn + ni * 8 + tg2;
                float* p = out + ((size_t)bhz * Lq + r) * Lq + c;
                float2 v0, v1;
                v0.x = fmaxf(acc[mi][ni][0] + b2, 0.0f);
                v0.y = fmaxf(acc[mi][ni][1] + b2, 0.0f);
                v1.x = fmaxf(acc[mi][ni][2] + b2, 0.0f);
                v1.y = fmaxf(acc[mi][ni][3] + b2, 0.0f);
                *(float2*)p            = v0;
                *(float2*)(p + 8 * Lq) = v1;
            }
        }
    }
}

// ---------------------------------------------------------------------------
extern "C" void kernel_launch(void* const* d_in, const int* in_sizes, int n_in,
                              void* d_out, int out_size)
{
    const float* X  = (const float*)d_in[0];
    const float* Y  = (const float*)d_in[1];
    const float* W1 = (const float*)d_in[2];
    const float* b1 = (const float*)d_in[3];
    const float* w2 = (const float*)d_in[4];
    const float* b2 = (const float*)d_in[5];
    float* out = (float*)d_out;

    const int s1_smem = (2 * 128 * SA + 2 * 64 * SA) * 2 + 2 * 64 * 4;  // 55808
    cudaFuncSetAttribute(stage1_kernel,
                         cudaFuncAttributeMaxDynamicSharedMemorySize, s1_smem);
    stage1_kernel<<<dim3(BH * Lq / 128, 2, 1), 256, s1_smem>>>(X, Y, W1, b1, w2);

    const int s2_smem = 6 * TILE_B;                                     // 110592
    cudaFuncSetAttribute(stage2_mma,
                         cudaFuncAttributeMaxDynamicSharedMemorySize, s2_smem);
    stage2_mma<<<dim3(8, 4, BH), 256, s2_smem>>>(b2, out);
}

// round 7
// speedup vs baseline: 1.0980x; 1.0980x over previous
#include <cuda_runtime.h>
#include <cuda_bf16.h>
#include <cuda_fp16.h>
#include <cstdint>

#define BH 32
#define Lq 1024
#define Dd 64

// Scratch: fp16 split of projected activations.
//   A = (X @ W1^T + b1) * w2  -> g_Xhi + g_Xlo (fp16 hi/lo split)
//   B = (Y @ W1^T + b1)       -> g_Yhi (fp16, truncated)
__device__ __half g_Xhi[BH * Lq * Dd];
__device__ __half g_Xlo[BH * Lq * Dd];
__device__ __half g_Yhi[BH * Lq * Dd];

// ======================== helpers ===========================
__device__ __forceinline__ uint32_t smem_u32(const void* p) {
    uint32_t a;
    asm("{ .reg .u64 t; cvta.to.shared.u64 t, %1; cvt.u32.u64 %0, t; }"
        : "=r"(a) : "l"(p));
    return a;
}
#define CP16(dst, src) \
    asm volatile("cp.async.cg.shared.global [%0], [%1], 16;" :: "r"(dst), "l"(src) : "memory")
#define CP_COMMIT() asm volatile("cp.async.commit_group;" ::: "memory")
#define CP_WAIT0()  asm volatile("cp.async.wait_group 0;" ::: "memory")

__device__ __forceinline__ void ldm4(uint32_t* r, uint32_t addr) {
    asm volatile("ldmatrix.sync.aligned.m8n8.x4.shared.b16 {%0,%1,%2,%3}, [%4];"
                 : "=r"(r[0]), "=r"(r[1]), "=r"(r[2]), "=r"(r[3]) : "r"(addr));
}
__device__ __forceinline__ void mma_bf16(float* c, const uint32_t* a, const uint32_t* b) {
    asm volatile(
        "mma.sync.aligned.m16n8k16.row.col.f32.bf16.bf16.f32 "
        "{%0,%1,%2,%3}, {%4,%5,%6,%7}, {%8,%9}, {%0,%1,%2,%3};"
        : "+f"(c[0]), "+f"(c[1]), "+f"(c[2]), "+f"(c[3])
        : "r"(a[0]), "r"(a[1]), "r"(a[2]), "r"(a[3]), "r"(b[0]), "r"(b[1]));
}
__device__ __forceinline__ void mma_f16(float* c, const uint32_t* a, const uint32_t* b) {
    asm volatile(
        "mma.sync.aligned.m16n8k16.row.col.f32.f16.f16.f32 "
        "{%0,%1,%2,%3}, {%4,%5,%6,%7}, {%8,%9}, {%0,%1,%2,%3};"
        : "+f"(c[0]), "+f"(c[1]), "+f"(c[2]), "+f"(c[3])
        : "r"(a[0]), "r"(a[1]), "r"(a[2]), "r"(a[3]), "r"(b[0]), "r"(b[1]));
}
__device__ __forceinline__ uint32_t pck(__nv_bfloat16 a, __nv_bfloat16 b) {
    __nv_bfloat162 t; t.x = a; t.y = b;
    return *(uint32_t*)&t;
}
__device__ __forceinline__ uint32_t pckh(__half a, __half b) {
    __half2 t; t.x = a; t.y = b;
    return *(uint32_t*)&t;
}
__device__ __forceinline__ void split4(float4 v, uint2& h, uint2& l) {
    __nv_bfloat16 h0 = __float2bfloat16(v.x), h1 = __float2bfloat16(v.y);
    __nv_bfloat16 h2 = __float2bfloat16(v.z), h3 = __float2bfloat16(v.w);
    __nv_bfloat16 l0 = __float2bfloat16(v.x - __bfloat162float(h0));
    __nv_bfloat16 l1 = __float2bfloat16(v.y - __bfloat162float(h1));
    __nv_bfloat16 l2 = __float2bfloat16(v.z - __bfloat162float(h2));
    __nv_bfloat16 l3 = __float2bfloat16(v.w - __bfloat162float(h3));
    h.x = pck(h0, h1); h.y = pck(h2, h3);
    l.x = pck(l0, l1); l.y = pck(l2, l3);
}

#define SA 72   // 16-bit tile stride (144 B rows)

__device__ __forceinline__ uint32_t fr(const __nv_bfloat16* t, int row, int k) {
    return *(const uint32_t*)(t + row * SA + k);
}

// ---------------------------------------------------------------------------
// Stage 1: projection as bf16 3-term HMMA GEMM, epilogue -> fp16 split.
// grid = (256, 2); block = 256. X path stores hi+lo; Y path stores hi only.
// ---------------------------------------------------------------------------
__global__ __launch_bounds__(256) void stage1_kernel(
    const float* __restrict__ X, const float* __restrict__ Y,
    const float* __restrict__ W1, const float* __restrict__ b1,
    const float* __restrict__ w2)
{
    extern __shared__ __nv_bfloat16 s1[];
    __nv_bfloat16* sXhi = s1;
    __nv_bfloat16* sXlo = s1 + 128 * SA;
    __nv_bfloat16* sWhi = s1 + 2 * 128 * SA;
    __nv_bfloat16* sWlo = sWhi + 64 * SA;
    float* sb1 = (float*)(sWlo + 64 * SA);
    float* sw2 = sb1 + 64;

    const int tid = threadIdx.x;
    const bool isX = (blockIdx.y == 0);
    const float* __restrict__ src = isX ? X : Y;
    const int rowBase = blockIdx.x * 128;

    {
        const float4* w4 = (const float4*)W1;
        #pragma unroll
        for (int i = 0; i < 4; ++i) {
            int idx = tid + i * 256;
            int d = idx >> 4, kq = idx & 15;
            uint2 h, l;
            split4(w4[idx], h, l);
            *(uint2*)&sWhi[d * SA + kq * 4] = h;
            *(uint2*)&sWlo[d * SA + kq * 4] = l;
        }
    }
    {
        const float4* x4 = (const float4*)(src + (size_t)rowBase * 64);
        #pragma unroll
        for (int i = 0; i < 8; ++i) {
            int idx = tid + i * 256;
            int r = idx >> 4, kq = idx & 15;
            uint2 h, l;
            split4(x4[idx], h, l);
            *(uint2*)&sXhi[r * SA + kq * 4] = h;
            *(uint2*)&sXlo[r * SA + kq * 4] = l;
        }
    }
    if (tid < 64) { sb1[tid] = b1[tid]; sw2[tid] = w2[tid]; }
    __syncthreads();

    const int wid = tid >> 5, lane = tid & 31;
    const int wm = (wid >> 1) * 32;
    const int wn = (wid & 1) * 32;
    const int g = lane >> 2, tg2 = (lane & 3) * 2;

    float acc[2][4][4];
    #pragma unroll
    for (int mi = 0; mi < 2; ++mi)
        #pragma unroll
        for (int ni = 0; ni < 4; ++ni)
            #pragma unroll
            for (int q = 0; q < 4; ++q) acc[mi][ni][q] = 0.0f;

    #pragma unroll
    for (int ks = 0; ks < 4; ++ks) {
        const int k0 = ks * 16;
        uint32_t a[2][4], bh[4][2], bl[4][2];
        #pragma unroll
        for (int ni = 0; ni < 4; ++ni) {
            int n = wn + ni * 8 + g;
            bh[ni][0] = fr(sWhi, n, k0 + tg2);
            bh[ni][1] = fr(sWhi, n, k0 + tg2 + 8);
            bl[ni][0] = fr(sWlo, n, k0 + tg2);
            bl[ni][1] = fr(sWlo, n, k0 + tg2 + 8);
        }
        #pragma unroll
        for (int mi = 0; mi < 2; ++mi) {
            int r = wm + mi * 16;
            a[mi][0] = fr(sXhi, r + g,     k0 + tg2);
            a[mi][1] = fr(sXhi, r + g + 8, k0 + tg2);
            a[mi][2] = fr(sXhi, r + g,     k0 + tg2 + 8);
            a[mi][3] = fr(sXhi, r + g + 8, k0 + tg2 + 8);
        }
        #pragma unroll
        for (int mi = 0; mi < 2; ++mi)
            #pragma unroll
            for (int ni = 0; ni < 4; ++ni) {
                mma_bf16(acc[mi][ni], a[mi], bh[ni]);
                mma_bf16(acc[mi][ni], a[mi], bl[ni]);
            }
        #pragma unroll
        for (int mi = 0; mi < 2; ++mi) {
            int r = wm + mi * 16;
            a[mi][0] = fr(sXlo, r + g,     k0 + tg2);
            a[mi][1] = fr(sXlo, r + g + 8, k0 + tg2);
            a[mi][2] = fr(sXlo, r + g,     k0 + tg2 + 8);
            a[mi][3] = fr(sXlo, r + g + 8, k0 + tg2 + 8);
        }
        #pragma unroll
        for (int mi = 0; mi < 2; ++mi)
            #pragma unroll
            for (int ni = 0; ni < 4; ++ni)
                mma_bf16(acc[mi][ni], a[mi], bh[ni]);
    }

    // epilogue: +b1; X path: *w2, fp16 hi/lo; Y path: fp16 hi only
    #pragma unroll
    for (int mi = 0; mi < 2; ++mi) {
        #pragma unroll
        for (int ni = 0; ni < 4; ++ni) {
            const int col = wn + ni * 8 + tg2;
            float ba = sb1[col], bb = sb1[col + 1];
            float wa = sw2[col], wb = sw2[col + 1];
            const float* c = acc[mi][ni];
            #pragma unroll
            for (int half = 0; half < 2; ++half) {
                int row = rowBase + wm + mi * 16 + g + half * 8;
                float v0 = c[2 * half + 0] + ba;
                float v1 = c[2 * half + 1] + bb;
                size_t eoff = (size_t)row * 64 + col;
                if (isX) {
                    v0 *= wa; v1 *= wb;
                    __half h0 = __float2half_rn(v0);
                    __half h1 = __float2half_rn(v1);
                    __half l0 = __float2half_rn(v0 - __half2float(h0));
                    __half l1 = __float2half_rn(v1 - __half2float(h1));
                    *(uint32_t*)(g_Xhi + eoff) = pckh(h0, h1);
                    *(uint32_t*)(g_Xlo + eoff) = pckh(l0, l1);
                } else {
                    *(uint32_t*)(g_Yhi + eoff) =
                        pckh(__float2half_rn(v0), __float2half_rn(v1));
                }
            }
        }
    }
}

// ---------------------------------------------------------------------------
// Stage 2: fp16 2-term HMMA GEMM (R4 skeleton).
// grid = (8, 8, 32), block = 256 (8 warps, 64x32 warp tile), smem = 54 KB.
// D = relu( Ahi.Bhi^T + Alo.Bhi^T + b2 )
// ---------------------------------------------------------------------------
#define T_AHI 0u
#define T_ALO 18432u
#define T_BHI 36864u

__global__ __launch_bounds__(256, 2) void stage2_mma(
    const float* __restrict__ b2p, float* __restrict__ out)
{
    extern __shared__ __half sm2[];
    const uint32_t sb = smem_u32(sm2);

    const int tid  = threadIdx.x;
    const int bhz  = blockIdx.z;
    const int mBase = blockIdx.y * 128;
    const int nBase = blockIdx.x * 128;

    // ---- async fills: three 128x64 fp16 tiles into stride-144B smem
    {
        const uint4* srcs[3] = {
            (const uint4*)(g_Xhi + (size_t)(bhz * Lq + mBase) * 64),
            (const uint4*)(g_Xlo + (size_t)(bhz * Lq + mBase) * 64),
            (const uint4*)(g_Yhi + (size_t)(bhz * Lq + nBase) * 64)};
        const uint32_t dsts[3] = {T_AHI, T_ALO, T_BHI};
        #pragma unroll
        for (int t = 0; t < 3; ++t) {
            const uint4* s = srcs[t];
            uint32_t db = sb + dsts[t];
            #pragma unroll
            for (int i = 0; i < 4; ++i) {
                int idx = tid + i * 256;             // 1024 x 16B chunks
                int row = idx >> 3, c = idx & 7;
                CP16(db + (uint32_t)row * 144 + (uint32_t)c * 16, s + idx);
            }
        }
        CP_COMMIT();
    }

    // ---- per-lane ldmatrix addresses (while loads fly)
    const int wid = tid >> 5, lane = tid & 31;
    const int wm = (wid >> 2) * 64;
    const int wn = (wid & 3) * 32;
    const int g = lane >> 2, tg2 = (lane & 3) * 2;

    const uint32_t aoff =
        (uint32_t)(wm + (lane & 7) + ((lane >> 3) & 1) * 8) * 144 +
        (uint32_t)((lane >> 4) * 8) * 2;
    const uint32_t uaAhi = sb + T_AHI + aoff;
    const uint32_t uaAlo = sb + T_ALO + aoff;
    uint32_t uaBhi[2];
    #pragma unroll
    for (int p = 0; p < 2; ++p) {
        uint32_t boff =
            (uint32_t)(wn + p * 16 + (lane & 7) + ((lane >> 4) & 1) * 8) * 144 +
            (uint32_t)(((lane >> 3) & 1) * 8) * 2;
        uaBhi[p] = sb + T_BHI + boff;
    }
    const float b2 = __ldg(b2p);

    float acc[4][4][4];
    #pragma unroll
    for (int mi = 0; mi < 4; ++mi)
        #pragma unroll
        for (int ni = 0; ni < 4; ++ni)
            #pragma unroll
            for (int q = 0; q < 4; ++q) acc[mi][ni][q] = 0.0f;

    CP_WAIT0();
    __syncthreads();

    #pragma unroll
    for (int ks = 0; ks < 4; ++ks) {
        const uint32_t kb = (uint32_t)ks * 32;       // 16 halves = 32 B
        uint32_t a[4][4], bhf[2][4];
        ldm4(bhf[0], uaBhi[0] + kb);
        ldm4(bhf[1], uaBhi[1] + kb);
        #pragma unroll
        for (int mi = 0; mi < 4; ++mi) ldm4(a[mi], uaAhi + mi * 2304u + kb);
        #pragma unroll
        for (int mi = 0; mi < 4; ++mi)
            #pragma unroll
            for (int ni = 0; ni < 4; ++ni)
                mma_f16(acc[mi][ni], a[mi], &bhf[ni >> 1][(ni & 1) * 2]);
        #pragma unroll
        for (int mi = 0; mi < 4; ++mi) ldm4(a[mi], uaAlo + mi * 2304u + kb);
        #pragma unroll
        for (int mi = 0; mi < 4; ++mi)
            #pragma unroll
            for (int ni = 0; ni < 4; ++ni)
                mma_f16(acc[mi][ni], a[mi], &bhf[ni >> 1][(ni & 1) * 2]);
    }

    // ---- epilogue: +b2, relu, float2 stores
    #pragma unroll
    for (int mi = 0; mi < 4; ++mi) {
        #pragma unroll
        for (int ni = 0; ni < 4; ++ni) {
            int r = mBase + wm + mi * 16 + g;
            int c = nBase + wn + ni * 8 + tg2;
            float* p = out + ((size_t)bhz * Lq + r) * Lq + c;
            float2 v0, v1;
            v0.x = fmaxf(acc[mi][ni][0] + b2, 0.0f);
            v0.y = fmaxf(acc[mi][ni][1] + b2, 0.0f);
            v1.x = fmaxf(acc[mi][ni][2] + b2, 0.0f);
            v1.y = fmaxf(acc[mi][ni][3] + b2, 0.0f);
            *(float2*)p            = v0;
            *(float2*)(p + 8 * Lq) = v1;
        }
    }
}

// ---------------------------------------------------------------------------
extern "C" void kernel_launch(void* const* d_in, const int* in_sizes, int n_in,
                              void* d_out, int out_size)
{
    const float* X  = (const float*)d_in[0];
    const float* Y  = (const float*)d_in[1];
    const float* W1 = (const float*)d_in[2];
    const float* b1 = (const float*)d_in[3];
    const float* w2 = (const float*)d_in[4];
    const float* b2 = (const float*)d_in[5];
    float* out = (float*)d_out;

    const int s1_smem = (2 * 128 * SA + 2 * 64 * SA) * 2 + 2 * 64 * 4;  // 55808
    cudaFuncSetAttribute(stage1_kernel,
                         cudaFuncAttributeMaxDynamicSharedMemorySize, s1_smem);
    stage1_kernel<<<dim3(BH * Lq / 128, 2, 1), 256, s1_smem>>>(X, Y, W1, b1, w2);

    const int s2_smem = 3 * 18432;                                      // 55296
    cudaFuncSetAttribute(stage2_mma,
                         cudaFuncAttributeMaxDynamicSharedMemorySize, s2_smem);
    stage2_mma<<<dim3(8, 8, BH), 256, s2_smem>>>(b2, out);
}

// round 9
// speedup vs baseline: 1.1414x; 1.0395x over previous
#include <cuda_runtime.h>
#include <cuda_bf16.h>
#include <cuda_fp16.h>
#include <cstdint>

#define BH 32
#define Lq 1024
#define Dd 64

// Scratch: fp16 split of projected activations.
//   A = (X @ W1^T + b1) * w2  -> g_Xhi + g_Xlo (fp16 hi/lo split)
//   B = (Y @ W1^T + b1)       -> g_Yhi (fp16, truncated)
__device__ __half g_Xhi[BH * Lq * Dd];
__device__ __half g_Xlo[BH * Lq * Dd];
__device__ __half g_Yhi[BH * Lq * Dd];

// ======================== helpers ===========================
__device__ __forceinline__ uint32_t smem_u32(const void* p) {
    uint32_t a;
    asm("{ .reg .u64 t; cvta.to.shared.u64 t, %1; cvt.u32.u64 %0, t; }"
        : "=r"(a) : "l"(p));
    return a;
}
#define CP16(dst, src) \
    asm volatile("cp.async.cg.shared.global [%0], [%1], 16;" :: "r"(dst), "l"(src) : "memory")
#define CP_COMMIT() asm volatile("cp.async.commit_group;" ::: "memory")
#define CP_WAIT0()  asm volatile("cp.async.wait_group 0;" ::: "memory")

__device__ __forceinline__ void ldm4(uint32_t* r, uint32_t addr) {
    asm volatile("ldmatrix.sync.aligned.m8n8.x4.shared.b16 {%0,%1,%2,%3}, [%4];"
                 : "=r"(r[0]), "=r"(r[1]), "=r"(r[2]), "=r"(r[3]) : "r"(addr));
}
__device__ __forceinline__ void mma_bf16(float* c, const uint32_t* a, const uint32_t* b) {
    asm volatile(
        "mma.sync.aligned.m16n8k16.row.col.f32.bf16.bf16.f32 "
        "{%0,%1,%2,%3}, {%4,%5,%6,%7}, {%8,%9}, {%0,%1,%2,%3};"
        : "+f"(c[0]), "+f"(c[1]), "+f"(c[2]), "+f"(c[3])
        : "r"(a[0]), "r"(a[1]), "r"(a[2]), "r"(a[3]), "r"(b[0]), "r"(b[1]));
}
__device__ __forceinline__ void mma_f16(float* c, const uint32_t* a, const uint32_t* b) {
    asm volatile(
        "mma.sync.aligned.m16n8k16.row.col.f32.f16.f16.f32 "
        "{%0,%1,%2,%3}, {%4,%5,%6,%7}, {%8,%9}, {%0,%1,%2,%3};"
        : "+f"(c[0]), "+f"(c[1]), "+f"(c[2]), "+f"(c[3])
        : "r"(a[0]), "r"(a[1]), "r"(a[2]), "r"(a[3]), "r"(b[0]), "r"(b[1]));
}
__device__ __forceinline__ uint32_t pck(__nv_bfloat16 a, __nv_bfloat16 b) {
    __nv_bfloat162 t; t.x = a; t.y = b;
    return *(uint32_t*)&t;
}
__device__ __forceinline__ uint32_t pckh(__half a, __half b) {
    __half2 t; t.x = a; t.y = b;
    return *(uint32_t*)&t;
}
__device__ __forceinline__ void split4(float4 v, uint2& h, uint2& l) {
    __nv_bfloat16 h0 = __float2bfloat16(v.x), h1 = __float2bfloat16(v.y);
    __nv_bfloat16 h2 = __float2bfloat16(v.z), h3 = __float2bfloat16(v.w);
    __nv_bfloat16 l0 = __float2bfloat16(v.x - __bfloat162float(h0));
    __nv_bfloat16 l1 = __float2bfloat16(v.y - __bfloat162float(h1));
    __nv_bfloat16 l2 = __float2bfloat16(v.z - __bfloat162float(h2));
    __nv_bfloat16 l3 = __float2bfloat16(v.w - __bfloat162float(h3));
    h.x = pck(h0, h1); h.y = pck(h2, h3);
    l.x = pck(l0, l1); l.y = pck(l2, l3);
}

#define SA 72   // 16-bit tile stride (144 B rows)

__device__ __forceinline__ uint32_t fr(const __nv_bfloat16* t, int row, int k) {
    return *(const uint32_t*)(t + row * SA + k);
}

// ---------------------------------------------------------------------------
// Stage 1: projection as bf16 3-term HMMA GEMM, epilogue -> fp16 split.
// (unchanged from R7 — on target)
// ---------------------------------------------------------------------------
__global__ __launch_bounds__(256) void stage1_kernel(
    const float* __restrict__ X, const float* __restrict__ Y,
    const float* __restrict__ W1, const float* __restrict__ b1,
    const float* __restrict__ w2)
{
    extern __shared__ __nv_bfloat16 s1[];
    __nv_bfloat16* sXhi = s1;
    __nv_bfloat16* sXlo = s1 + 128 * SA;
    __nv_bfloat16* sWhi = s1 + 2 * 128 * SA;
    __nv_bfloat16* sWlo = sWhi + 64 * SA;
    float* sb1 = (float*)(sWlo + 64 * SA);
    float* sw2 = sb1 + 64;

    const int tid = threadIdx.x;
    const bool isX = (blockIdx.y == 0);
    const float* __restrict__ src = isX ? X : Y;
    const int rowBase = blockIdx.x * 128;

    {
        const float4* w4 = (const float4*)W1;
        #pragma unroll
        for (int i = 0; i < 4; ++i) {
            int idx = tid + i * 256;
            int d = idx >> 4, kq = idx & 15;
            uint2 h, l;
            split4(w4[idx], h, l);
            *(uint2*)&sWhi[d * SA + kq * 4] = h;
            *(uint2*)&sWlo[d * SA + kq * 4] = l;
        }
    }
    {
        const float4* x4 = (const float4*)(src + (size_t)rowBase * 64);
        #pragma unroll
        for (int i = 0; i < 8; ++i) {
            int idx = tid + i * 256;
            int r = idx >> 4, kq = idx & 15;
            uint2 h, l;
            split4(x4[idx], h, l);
            *(uint2*)&sXhi[r * SA + kq * 4] = h;
            *(uint2*)&sXlo[r * SA + kq * 4] = l;
        }
    }
    if (tid < 64) { sb1[tid] = b1[tid]; sw2[tid] = w2[tid]; }
    __syncthreads();

    const int wid = tid >> 5, lane = tid & 31;
    const int wm = (wid >> 1) * 32;
    const int wn = (wid & 1) * 32;
    const int g = lane >> 2, tg2 = (lane & 3) * 2;

    float acc[2][4][4];
    #pragma unroll
    for (int mi = 0; mi < 2; ++mi)
        #pragma unroll
        for (int ni = 0; ni < 4; ++ni)
            #pragma unroll
            for (int q = 0; q < 4; ++q) acc[mi][ni][q] = 0.0f;

    #pragma unroll
    for (int ks = 0; ks < 4; ++ks) {
        const int k0 = ks * 16;
        uint32_t a[2][4], bh[4][2], bl[4][2];
        #pragma unroll
        for (int ni = 0; ni < 4; ++ni) {
            int n = wn + ni * 8 + g;
            bh[ni][0] = fr(sWhi, n, k0 + tg2);
            bh[ni][1] = fr(sWhi, n, k0 + tg2 + 8);
            bl[ni][0] = fr(sWlo, n, k0 + tg2);
            bl[ni][1] = fr(sWlo, n, k0 + tg2 + 8);
        }
        #pragma unroll
        for (int mi = 0; mi < 2; ++mi) {
            int r = wm + mi * 16;
            a[mi][0] = fr(sXhi, r + g,     k0 + tg2);
            a[mi][1] = fr(sXhi, r + g + 8, k0 + tg2);
            a[mi][2] = fr(sXhi, r + g,     k0 + tg2 + 8);
            a[mi][3] = fr(sXhi, r + g + 8, k0 + tg2 + 8);
        }
        #pragma unroll
        for (int mi = 0; mi < 2; ++mi)
            #pragma unroll
            for (int ni = 0; ni < 4; ++ni) {
                mma_bf16(acc[mi][ni], a[mi], bh[ni]);
                mma_bf16(acc[mi][ni], a[mi], bl[ni]);
            }
        #pragma unroll
        for (int mi = 0; mi < 2; ++mi) {
            int r = wm + mi * 16;
            a[mi][0] = fr(sXlo, r + g,     k0 + tg2);
            a[mi][1] = fr(sXlo, r + g + 8, k0 + tg2);
            a[mi][2] = fr(sXlo, r + g,     k0 + tg2 + 8);
            a[mi][3] = fr(sXlo, r + g + 8, k0 + tg2 + 8);
        }
        #pragma unroll
        for (int mi = 0; mi < 2; ++mi)
            #pragma unroll
            for (int ni = 0; ni < 4; ++ni)
                mma_bf16(acc[mi][ni], a[mi], bh[ni]);
    }

    #pragma unroll
    for (int mi = 0; mi < 2; ++mi) {
        #pragma unroll
        for (int ni = 0; ni < 4; ++ni) {
            const int col = wn + ni * 8 + tg2;
            float ba = sb1[col], bb = sb1[col + 1];
            float wa = sw2[col], wb = sw2[col + 1];
            const float* c = acc[mi][ni];
            #pragma unroll
            for (int half = 0; half < 2; ++half) {
                int row = rowBase + wm + mi * 16 + g + half * 8;
                float v0 = c[2 * half + 0] + ba;
                float v1 = c[2 * half + 1] + bb;
                size_t eoff = (size_t)row * 64 + col;
                if (isX) {
                    v0 *= wa; v1 *= wb;
                    __half h0 = __float2half_rn(v0);
                    __half h1 = __float2half_rn(v1);
                    __half l0 = __float2half_rn(v0 - __half2float(h0));
                    __half l1 = __float2half_rn(v1 - __half2float(h1));
                    *(uint32_t*)(g_Xhi + eoff) = pckh(h0, h1);
                    *(uint32_t*)(g_Xlo + eoff) = pckh(l0, l1);
                } else {
                    *(uint32_t*)(g_Yhi + eoff) =
                        pckh(__float2half_rn(v0), __float2half_rn(v1));
                }
            }
        }
    }
}

// ---------------------------------------------------------------------------
// Stage 2: fp16 2-term HMMA GEMM, 64x128 CTA tile, 3 CTAs/SM.
// grid = (8, 16, 32) = 4096, block = 256 (8 warps, 32x32 warp tile).
// smem = 36864 B: Ahi [64][72] | Alo [64][72] | Bhi [128][72]
// D = relu( Ahi.Bhi^T + Alo.Bhi^T + b2 )
// ---------------------------------------------------------------------------
#define T_ALO2 9216u
#define T_BHI2 18432u

__global__ __launch_bounds__(256, 3) void stage2_mma(
    const float* __restrict__ b2p, float* __restrict__ out)
{
    extern __shared__ __half sm2[];
    const uint32_t sb = smem_u32(sm2);

    const int tid  = threadIdx.x;
    const int bhz  = blockIdx.z;
    const int mBase = blockIdx.y * 64;
    const int nBase = blockIdx.x * 128;

    // ---- async fills: A hi/lo (64x64 each) + B hi (128x64)
    {
        const uint4* aHi = (const uint4*)(g_Xhi + (size_t)(bhz * Lq + mBase) * 64);
        const uint4* aLo = (const uint4*)(g_Xlo + (size_t)(bhz * Lq + mBase) * 64);
        #pragma unroll
        for (int i = 0; i < 2; ++i) {
            int idx = tid + i * 256;                 // 512 x 16B chunks
            int row = idx >> 3, c = idx & 7;
            uint32_t so = (uint32_t)row * 144 + (uint32_t)c * 16;
            CP16(sb + so, aHi + idx);
            CP16(sb + T_ALO2 + so, aLo + idx);
        }
        const uint4* bHi = (const uint4*)(g_Yhi + (size_t)(bhz * Lq + nBase) * 64);
        #pragma unroll
        for (int i = 0; i < 4; ++i) {
            int idx = tid + i * 256;                 // 1024 x 16B chunks
            int row = idx >> 3, c = idx & 7;
            CP16(sb + T_BHI2 + (uint32_t)row * 144 + (uint32_t)c * 16, bHi + idx);
        }
        CP_COMMIT();
    }

    // ---- per-lane ldmatrix addresses (while loads fly)
    const int wid = tid >> 5, lane = tid & 31;
    const int wm = (wid >> 2) * 32;                  // 2 M groups of 32
    const int wn = (wid & 3) * 32;                   // 4 N groups of 32
    const int g = lane >> 2, tg2 = (lane & 3) * 2;

    const uint32_t aoff =
        (uint32_t)(wm + (lane & 7) + ((lane >> 3) & 1) * 8) * 144 +
        (uint32_t)((lane >> 4) * 8) * 2;
    const uint32_t uaAhi = sb + aoff;
    const uint32_t uaAlo = sb + T_ALO2 + aoff;
    uint32_t uaBhi[2];
    #pragma unroll
    for (int p = 0; p < 2; ++p) {
        uint32_t boff =
            (uint32_t)(wn + p * 16 + (lane & 7) + ((lane >> 4) & 1) * 8) * 144 +
            (uint32_t)(((lane >> 3) & 1) * 8) * 2;
        uaBhi[p] = sb + T_BHI2 + boff;
    }
    const float b2 = __ldg(b2p);

    float acc[2][4][4];
    #pragma unroll
    for (int mi = 0; mi < 2; ++mi)
        #pragma unroll
        for (int ni = 0; ni < 4; ++ni)
            #pragma unroll
            for (int q = 0; q < 4; ++q) acc[mi][ni][q] = 0.0f;

    CP_WAIT0();
    __syncthreads();

    #pragma unroll
    for (int ks = 0; ks < 4; ++ks) {
        const uint32_t kb = (uint32_t)ks * 32;       // 16 halves = 32 B
        uint32_t a[2][4], bhf[2][4];
        ldm4(bhf[0], uaBhi[0] + kb);
        ldm4(bhf[1], uaBhi[1] + kb);
        ldm4(a[0], uaAhi + kb);
        ldm4(a[1], uaAhi + 2304u + kb);
        #pragma unroll
        for (int mi = 0; mi < 2; ++mi)
            #pragma unroll
            for (int ni = 0; ni < 4; ++ni)
                mma_f16(acc[mi][ni], a[mi], &bhf[ni >> 1][(ni & 1) * 2]);
        ldm4(a[0], uaAlo + kb);
        ldm4(a[1], uaAlo + 2304u + kb);
        #pragma unroll
        for (int mi = 0; mi < 2; ++mi)
            #pragma unroll
            for (int ni = 0; ni < 4; ++ni)
                mma_f16(acc[mi][ni], a[mi], &bhf[ni >> 1][(ni & 1) * 2]);
    }

    // ---- epilogue: +b2, relu, float2 stores
    #pragma unroll
    for (int mi = 0; mi < 2; ++mi) {
        #pragma unroll
        for (int ni = 0; ni < 4; ++ni) {
            int r = mBase + wm + mi * 16 + g;
            int c = nBase + wn + ni * 8 + tg2;
            float* p = out + ((size_t)bhz * Lq + r) * Lq + c;
            float2 v0, v1;
            v0.x = fmaxf(acc[mi][ni][0] + b2, 0.0f);
            v0.y = fmaxf(acc[mi][ni][1] + b2, 0.0f);
            v1.x = fmaxf(acc[mi][ni][2] + b2, 0.0f);
            v1.y = fmaxf(acc[mi][ni][3] + b2, 0.0f);
            *(float2*)p            = v0;
            *(float2*)(p + 8 * Lq) = v1;
        }
    }
}

// ---------------------------------------------------------------------------
extern "C" void kernel_launch(void* const* d_in, const int* in_sizes, int n_in,
                              void* d_out, int out_size)
{
    const float* X  = (const float*)d_in[0];
    const float* Y  = (const float*)d_in[1];
    const float* W1 = (const float*)d_in[2];
    const float* b1 = (const float*)d_in[3];
    const float* w2 = (const float*)d_in[4];
    const float* b2 = (const float*)d_in[5];
    float* out = (float*)d_out;

    const int s1_smem = (2 * 128 * SA + 2 * 64 * SA) * 2 + 2 * 64 * 4;  // 55808
    cudaFuncSetAttribute(stage1_kernel,
                         cudaFuncAttributeMaxDynamicSharedMemorySize, s1_smem);
    stage1_kernel<<<dim3(BH * Lq / 128, 2, 1), 256, s1_smem>>>(X, Y, W1, b1, w2);

    const int s2_smem = 36864;
    cudaFuncSetAttribute(stage2_mma,
                         cudaFuncAttributeMaxDynamicSharedMemorySize, s2_smem);
    stage2_mma<<<dim3(8, 16, BH), 256, s2_smem>>>(b2, out);
}

// round 13
// speedup vs baseline: 1.2312x; 1.0787x over previous
#include <cuda_runtime.h>
#include <cuda_bf16.h>
#include <cuda_fp16.h>
#include <cstdint>

#define BH 32
#define Lq 1024
#define Dd 64

// Scratch: fp16 projected activations.
//   A = (X @ W1^T + b1) * w2  -> g_Xh   (fp16)
//   B = (Y @ W1^T + b1)       -> g_Yh   (fp16)
__device__ __half g_Xh[BH * Lq * Dd];
__device__ __half g_Yh[BH * Lq * Dd];

// ======================== helpers ===========================
__device__ __forceinline__ uint32_t smem_u32(const void* p) {
    uint32_t a;
    asm("{ .reg .u64 t; cvta.to.shared.u64 t, %1; cvt.u32.u64 %0, t; }"
        : "=r"(a) : "l"(p));
    return a;
}
#define CP16(dst, src) \
    asm volatile("cp.async.cg.shared.global [%0], [%1], 16;" :: "r"(dst), "l"(src) : "memory")
#define CP_COMMIT() asm volatile("cp.async.commit_group;" ::: "memory")
#define CP_WAIT0()  asm volatile("cp.async.wait_group 0;" ::: "memory")

__device__ __forceinline__ void ldm4(uint32_t* r, uint32_t addr) {
    asm volatile("ldmatrix.sync.aligned.m8n8.x4.shared.b16 {%0,%1,%2,%3}, [%4];"
                 : "=r"(r[0]), "=r"(r[1]), "=r"(r[2]), "=r"(r[3]) : "r"(addr));
}
__device__ __forceinline__ void mma_bf16(float* c, const uint32_t* a, const uint32_t* b) {
    asm volatile(
        "mma.sync.aligned.m16n8k16.row.col.f32.bf16.bf16.f32 "
        "{%0,%1,%2,%3}, {%4,%5,%6,%7}, {%8,%9}, {%0,%1,%2,%3};"
        : "+f"(c[0]), "+f"(c[1]), "+f"(c[2]), "+f"(c[3])
        : "r"(a[0]), "r"(a[1]), "r"(a[2]), "r"(a[3]), "r"(b[0]), "r"(b[1]));
}
__device__ __forceinline__ void mma_f16(float* c, const uint32_t* a, const uint32_t* b) {
    asm volatile(
        "mma.sync.aligned.m16n8k16.row.col.f32.f16.f16.f32 "
        "{%0,%1,%2,%3}, {%4,%5,%6,%7}, {%8,%9}, {%0,%1,%2,%3};"
        : "+f"(c[0]), "+f"(c[1]), "+f"(c[2]), "+f"(c[3])
        : "r"(a[0]), "r"(a[1]), "r"(a[2]), "r"(a[3]), "r"(b[0]), "r"(b[1]));
}
__device__ __forceinline__ uint32_t pck(__nv_bfloat16 a, __nv_bfloat16 b) {
    __nv_bfloat162 t; t.x = a; t.y = b;
    return *(uint32_t*)&t;
}
__device__ __forceinline__ uint32_t pckh(__half a, __half b) {
    __half2 t; t.x = a; t.y = b;
    return *(uint32_t*)&t;
}
__device__ __forceinline__ void split4(float4 v, uint2& h, uint2& l) {
    __nv_bfloat16 h0 = __float2bfloat16(v.x), h1 = __float2bfloat16(v.y);
    __nv_bfloat16 h2 = __float2bfloat16(v.z), h3 = __float2bfloat16(v.w);
    __nv_bfloat16 l0 = __float2bfloat16(v.x - __bfloat162float(h0));
    __nv_bfloat16 l1 = __float2bfloat16(v.y - __bfloat162float(h1));
    __nv_bfloat16 l2 = __float2bfloat16(v.z - __bfloat162float(h2));
    __nv_bfloat16 l3 = __float2bfloat16(v.w - __bfloat162float(h3));
    h.x = pck(h0, h1); h.y = pck(h2, h3);
    l.x = pck(l0, l1); l.y = pck(l2, l3);
}

#define SA 72   // 16-bit tile stride (144 B rows)

__device__ __forceinline__ uint32_t fr(const __nv_bfloat16* t, int row, int k) {
    return *(const uint32_t*)(t + row * SA + k);
}

// ---------------------------------------------------------------------------
// Stage 1: projection as bf16 3-term HMMA GEMM, epilogue -> fp16 (hi only).
// grid = (256, 2); block = 256.
// ---------------------------------------------------------------------------
__global__ __launch_bounds__(256) void stage1_kernel(
    const float* __restrict__ X, const float* __restrict__ Y,
    const float* __restrict__ W1, const float* __restrict__ b1,
    const float* __restrict__ w2)
{
    extern __shared__ __nv_bfloat16 s1[];
    __nv_bfloat16* sXhi = s1;
    __nv_bfloat16* sXlo = s1 + 128 * SA;
    __nv_bfloat16* sWhi = s1 + 2 * 128 * SA;
    __nv_bfloat16* sWlo = sWhi + 64 * SA;
    float* sb1 = (float*)(sWlo + 64 * SA);
    float* sw2 = sb1 + 64;

    const int tid = threadIdx.x;
    const bool isX = (blockIdx.y == 0);
    const float* __restrict__ src = isX ? X : Y;
    __half* __restrict__ dst = isX ? g_Xh : g_Yh;
    const int rowBase = blockIdx.x * 128;

    {
        const float4* w4 = (const float4*)W1;
        #pragma unroll
        for (int i = 0; i < 4; ++i) {
            int idx = tid + i * 256;
            int d = idx >> 4, kq = idx & 15;
            uint2 h, l;
            split4(w4[idx], h, l);
            *(uint2*)&sWhi[d * SA + kq * 4] = h;
            *(uint2*)&sWlo[d * SA + kq * 4] = l;
        }
    }
    {
        const float4* x4 = (const float4*)(src + (size_t)rowBase * 64);
        #pragma unroll
        for (int i = 0; i < 8; ++i) {
            int idx = tid + i * 256;
            int r = idx >> 4, kq = idx & 15;
            uint2 h, l;
            split4(x4[idx], h, l);
            *(uint2*)&sXhi[r * SA + kq * 4] = h;
            *(uint2*)&sXlo[r * SA + kq * 4] = l;
        }
    }
    if (tid < 64) { sb1[tid] = b1[tid]; sw2[tid] = w2[tid]; }
    __syncthreads();

    const int wid = tid >> 5, lane = tid & 31;
    const int wm = (wid >> 1) * 32;
    const int wn = (wid & 1) * 32;
    const int g = lane >> 2, tg2 = (lane & 3) * 2;

    float acc[2][4][4];
    #pragma unroll
    for (int mi = 0; mi < 2; ++mi)
        #pragma unroll
        for (int ni = 0; ni < 4; ++ni)
            #pragma unroll
            for (int q = 0; q < 4; ++q) acc[mi][ni][q] = 0.0f;

    #pragma unroll
    for (int ks = 0; ks < 4; ++ks) {
        const int k0 = ks * 16;
        uint32_t a[2][4], bh[4][2], bl[4][2];
        #pragma unroll
        for (int ni = 0; ni < 4; ++ni) {
            int n = wn + ni * 8 + g;
            bh[ni][0] = fr(sWhi, n, k0 + tg2);
            bh[ni][1] = fr(sWhi, n, k0 + tg2 + 8);
            bl[ni][0] = fr(sWlo, n, k0 + tg2);
            bl[ni][1] = fr(sWlo, n, k0 + tg2 + 8);
        }
        #pragma unroll
        for (int mi = 0; mi < 2; ++mi) {
            int r = wm + mi * 16;
            a[mi][0] = fr(sXhi, r + g,     k0 + tg2);
            a[mi][1] = fr(sXhi, r + g + 8, k0 + tg2);
            a[mi][2] = fr(sXhi, r + g,     k0 + tg2 + 8);
            a[mi][3] = fr(sXhi, r + g + 8, k0 + tg2 + 8);
        }
        #pragma unroll
        for (int mi = 0; mi < 2; ++mi)
            #pragma unroll
            for (int ni = 0; ni < 4; ++ni) {
                mma_bf16(acc[mi][ni], a[mi], bh[ni]);
                mma_bf16(acc[mi][ni], a[mi], bl[ni]);
            }
        #pragma unroll
        for (int mi = 0; mi < 2; ++mi) {
            int r = wm + mi * 16;
            a[mi][0] = fr(sXlo, r + g,     k0 + tg2);
            a[mi][1] = fr(sXlo, r + g + 8, k0 + tg2);
            a[mi][2] = fr(sXlo, r + g,     k0 + tg2 + 8);
            a[mi][3] = fr(sXlo, r + g + 8, k0 + tg2 + 8);
        }
        #pragma unroll
        for (int mi = 0; mi < 2; ++mi)
            #pragma unroll
            for (int ni = 0; ni < 4; ++ni)
                mma_bf16(acc[mi][ni], a[mi], bh[ni]);
    }

    #pragma unroll
    for (int mi = 0; mi < 2; ++mi) {
        #pragma unroll
        for (int ni = 0; ni < 4; ++ni) {
            const int col = wn + ni * 8 + tg2;
            float ba = sb1[col], bb = sb1[col + 1];
            float wa = sw2[col], wb = sw2[col + 1];
            const float* c = acc[mi][ni];
            #pragma unroll
            for (int half = 0; half < 2; ++half) {
                int row = rowBase + wm + mi * 16 + g + half * 8;
                float v0 = c[2 * half + 0] + ba;
                float v1 = c[2 * half + 1] + bb;
                if (isX) { v0 *= wa; v1 *= wb; }
                size_t eoff = (size_t)row * 64 + col;
                *(uint32_t*)(dst + eoff) =
                    pckh(__float2half_rn(v0), __float2half_rn(v1));
            }
        }
    }
}

// ---------------------------------------------------------------------------
// Stage 2: pure fp16 HMMA GEMM, 64x128 CTA tile, smem-staged coalesced epi.
// grid = (8, 16, 32) = 4096, block = 256 (8 warps, 32x32 warp tile).
// smem (36864 B): tiles Ah [64][72] @0, Bh [128][72] @9216  (27648 B)
//                 overlaid after mainloop by 8 per-warp epi buffers [32][36] f32
// EPI_STRIDE=36 -> row pitch 144 B: all v4 accesses 16B-aligned.
// ---------------------------------------------------------------------------
#define T_BH2 9216u
#define EPI_STRIDE 36
#define EPI_WBYTES 4608u        // 32*36*4
#define S2_SMEM 36864

__global__ __launch_bounds__(256, 3) void stage2_mma(
    const float* __restrict__ b2p, float* __restrict__ out)
{
    extern __shared__ __half sm2[];
    const uint32_t sb = smem_u32(sm2);

    const int tid  = threadIdx.x;
    const int bhz  = blockIdx.z;
    const int mBase = blockIdx.y * 64;
    const int nBase = blockIdx.x * 128;

    // ---- async fills: A (64x64) + B (128x64)
    {
        const uint4* aH = (const uint4*)(g_Xh + (size_t)(bhz * Lq + mBase) * 64);
        #pragma unroll
        for (int i = 0; i < 2; ++i) {
            int idx = tid + i * 256;                 // 512 x 16B chunks
            int row = idx >> 3, c = idx & 7;
            CP16(sb + (uint32_t)row * 144 + (uint32_t)c * 16, aH + idx);
        }
        const uint4* bH = (const uint4*)(g_Yh + (size_t)(bhz * Lq + nBase) * 64);
        #pragma unroll
        for (int i = 0; i < 4; ++i) {
            int idx = tid + i * 256;                 // 1024 x 16B chunks
            int row = idx >> 3, c = idx & 7;
            CP16(sb + T_BH2 + (uint32_t)row * 144 + (uint32_t)c * 16, bH + idx);
        }
        CP_COMMIT();
    }

    // ---- per-lane ldmatrix addresses (while loads fly)
    const int wid = tid >> 5, lane = tid & 31;
    const int wm = (wid >> 2) * 32;                  // 2 M groups of 32
    const int wn = (wid & 3) * 32;                   // 4 N groups of 32
    const int g = lane >> 2, tg2 = (lane & 3) * 2;

    const uint32_t aoff =
        (uint32_t)(wm + (lane & 7) + ((lane >> 3) & 1) * 8) * 144 +
        (uint32_t)((lane >> 4) * 8) * 2;
    const uint32_t uaA = sb + aoff;
    uint32_t uaB[2];
    #pragma unroll
    for (int p = 0; p < 2; ++p) {
        uint32_t boff =
            (uint32_t)(wn + p * 16 + (lane & 7) + ((lane >> 4) & 1) * 8) * 144 +
            (uint32_t)(((lane >> 3) & 1) * 8) * 2;
        uaB[p] = sb + T_BH2 + boff;
    }
    const float b2 = __ldg(b2p);

    float acc[2][4][4];
    #pragma unroll
    for (int mi = 0; mi < 2; ++mi)
        #pragma unroll
        for (int ni = 0; ni < 4; ++ni)
            #pragma unroll
            for (int q = 0; q < 4; ++q) acc[mi][ni][q] = 0.0f;

    CP_WAIT0();
    __syncthreads();

    #pragma unroll
    for (int ks = 0; ks < 4; ++ks) {
        const uint32_t kb = (uint32_t)ks * 32;       // 16 halves = 32 B
        uint32_t a[2][4], bf[2][4];
        ldm4(bf[0], uaB[0] + kb);
        ldm4(bf[1], uaB[1] + kb);
        ldm4(a[0], uaA + kb);
        ldm4(a[1], uaA + 2304u + kb);
        #pragma unroll
        for (int mi = 0; mi < 2; ++mi)
            #pragma unroll
            for (int ni = 0; ni < 4; ++ni)
                mma_f16(acc[mi][ni], a[mi], &bf[ni >> 1][(ni & 1) * 2]);
    }

    // ---- epilogue: bias+relu in regs -> per-warp smem tile -> coalesced STG
    __syncthreads();                 // tiles dead; safe to overlay epi buffers
    const uint32_t ebuf = sb + (uint32_t)wid * EPI_WBYTES;

    #pragma unroll
    for (int mi = 0; mi < 2; ++mi) {
        #pragma unroll
        for (int ni = 0; ni < 4; ++ni) {
            #pragma unroll
            for (int half = 0; half < 2; ++half) {
                int row = mi * 16 + half * 8 + g;
                int col = ni * 8 + tg2;
                float2 v;
                v.x = fmaxf(acc[mi][ni][2 * half + 0] + b2, 0.0f);
                v.y = fmaxf(acc[mi][ni][2 * half + 1] + b2, 0.0f);
                asm volatile("st.shared.v2.f32 [%0], {%1, %2};"
                             :: "r"(ebuf + (uint32_t)(row * EPI_STRIDE + col) * 4),
                                "f"(v.x), "f"(v.y) : "memory");
            }
        }
    }
    __syncwarp();

    // each warp streams its own 32x32 tile: 8 iters x (4 rows x 8 lanes x 16B)
    const int er = lane >> 3;            // 0..3
    const int ec = (lane & 7) * 4;       // 0,4,...,28
    float* gout = out + ((size_t)bhz * Lq + mBase + wm) * Lq + nBase + wn;
    #pragma unroll
    for (int it = 0; it < 8; ++it) {
        int row = it * 4 + er;
        float4 v;
        asm volatile("ld.shared.v4.f32 {%0, %1, %2, %3}, [%4];"
                     : "=f"(v.x), "=f"(v.y), "=f"(v.z), "=f"(v.w)
                     : "r"(ebuf + (uint32_t)(row * EPI_STRIDE + ec) * 4));
        *(float4*)(gout + (size_t)row * Lq + ec) = v;
    }
}

// ---------------------------------------------------------------------------
extern "C" void kernel_launch(void* const* d_in, const int* in_sizes, int n_in,
                              void* d_out, int out_size)
{
    const float* X  = (const float*)d_in[0];
    const float* Y  = (const float*)d_in[1];
    const float* W1 = (const float*)d_in[2];
    const float* b1 = (const float*)d_in[3];
    const float* w2 = (const float*)d_in[4];
    const float* b2 = (const float*)d_in[5];
    float* out = (float*)d_out;

    const int s1_smem = (2 * 128 * SA + 2 * 64 * SA) * 2 + 2 * 64 * 4;  // 55808
    cudaFuncSetAttribute(stage1_kernel,
                         cudaFuncAttributeMaxDynamicSharedMemorySize, s1_smem);
    stage1_kernel<<<dim3(BH * Lq / 128, 2, 1), 256, s1_smem>>>(X, Y, W1, b1, w2);

    cudaFuncSetAttribute(stage2_mma,
                         cudaFuncAttributeMaxDynamicSharedMemorySize, S2_SMEM);
    stage2_mma<<<dim3(8, 16, BH), 256, S2_SMEM>>>(b2, out);
}

// round 16
// speedup vs baseline: 1.2693x; 1.0310x over previous
#include <cuda_runtime.h>
#include <cuda_bf16.h>
#include <cuda_fp16.h>
#include <cstdint>

#define BH 32
#define Lq 1024
#define Dd 64

// Scratch: fp16 projected activations.
//   A = (X @ W1^T + b1) * w2  -> g_Xh   (fp16)
//   B = (Y @ W1^T + b1)       -> g_Yh   (fp16)
__device__ __half g_Xh[BH * Lq * Dd];
__device__ __half g_Yh[BH * Lq * Dd];

// ======================== helpers ===========================
__device__ __forceinline__ uint32_t smem_u32(const void* p) {
    uint32_t a;
    asm("{ .reg .u64 t; cvta.to.shared.u64 t, %1; cvt.u32.u64 %0, t; }"
        : "=r"(a) : "l"(p));
    return a;
}
#define CP16(dst, src) \
    asm volatile("cp.async.cg.shared.global [%0], [%1], 16;" :: "r"(dst), "l"(src) : "memory")
#define CP_COMMIT() asm volatile("cp.async.commit_group;" ::: "memory")
#define CP_WAIT0()  asm volatile("cp.async.wait_group 0;" ::: "memory")

__device__ __forceinline__ void ldm4(uint32_t* r, uint32_t addr) {
    asm volatile("ldmatrix.sync.aligned.m8n8.x4.shared.b16 {%0,%1,%2,%3}, [%4];"
                 : "=r"(r[0]), "=r"(r[1]), "=r"(r[2]), "=r"(r[3]) : "r"(addr));
}
__device__ __forceinline__ void mma_bf16(float* c, const uint32_t* a, const uint32_t* b) {
    asm volatile(
        "mma.sync.aligned.m16n8k16.row.col.f32.bf16.bf16.f32 "
        "{%0,%1,%2,%3}, {%4,%5,%6,%7}, {%8,%9}, {%0,%1,%2,%3};"
        : "+f"(c[0]), "+f"(c[1]), "+f"(c[2]), "+f"(c[3])
        : "r"(a[0]), "r"(a[1]), "r"(a[2]), "r"(a[3]), "r"(b[0]), "r"(b[1]));
}
__device__ __forceinline__ void mma_f16(float* c, const uint32_t* a, const uint32_t* b) {
    asm volatile(
        "mma.sync.aligned.m16n8k16.row.col.f32.f16.f16.f32 "
        "{%0,%1,%2,%3}, {%4,%5,%6,%7}, {%8,%9}, {%0,%1,%2,%3};"
        : "+f"(c[0]), "+f"(c[1]), "+f"(c[2]), "+f"(c[3])
        : "r"(a[0]), "r"(a[1]), "r"(a[2]), "r"(a[3]), "r"(b[0]), "r"(b[1]));
}
__device__ __forceinline__ uint32_t pck(__nv_bfloat16 a, __nv_bfloat16 b) {
    __nv_bfloat162 t; t.x = a; t.y = b;
    return *(uint32_t*)&t;
}
__device__ __forceinline__ uint32_t pckh(__half a, __half b) {
    __half2 t; t.x = a; t.y = b;
    return *(uint32_t*)&t;
}
__device__ __forceinline__ void split4(float4 v, uint2& h, uint2& l) {
    __nv_bfloat16 h0 = __float2bfloat16(v.x), h1 = __float2bfloat16(v.y);
    __nv_bfloat16 h2 = __float2bfloat16(v.z), h3 = __float2bfloat16(v.w);
    __nv_bfloat16 l0 = __float2bfloat16(v.x - __bfloat162float(h0));
    __nv_bfloat16 l1 = __float2bfloat16(v.y - __bfloat162float(h1));
    __nv_bfloat16 l2 = __float2bfloat16(v.z - __bfloat162float(h2));
    __nv_bfloat16 l3 = __float2bfloat16(v.w - __bfloat162float(h3));
    h.x = pck(h0, h1); h.y = pck(h2, h3);
    l.x = pck(l0, l1); l.y = pck(l2, l3);
}

#define SA 72   // 16-bit tile stride (144 B rows)

// ---------------------------------------------------------------------------
// Stage 1: projection as bf16 3-term HMMA GEMM, ldmatrix frags + staged epi.
// grid = (256, 2); block = 256; smem 55808 B.
// Layout: sXhi@0 sXlo@18432 sWhi@36864 sWlo@46080 sb1@55296 sw2@55552
// Epilogue buffer overlays sXhi: [128] rows x 144 B pitch (72 halves).
// ---------------------------------------------------------------------------
#define S1_XLO 18432u
#define S1_WHI 36864u
#define S1_WLO 46080u
#define EP1_PITCH 144u          // bytes per row (72 halves; 64 used + pad)

__global__ __launch_bounds__(256) void stage1_kernel(
    const float* __restrict__ X, const float* __restrict__ Y,
    const float* __restrict__ W1, const float* __restrict__ b1,
    const float* __restrict__ w2)
{
    extern __shared__ __nv_bfloat16 s1[];
    const uint32_t sb = smem_u32(s1);
    __nv_bfloat16* sXhi = s1;
    __nv_bfloat16* sXlo = s1 + 128 * SA;
    __nv_bfloat16* sWhi = s1 + 2 * 128 * SA;
    __nv_bfloat16* sWlo = sWhi + 64 * SA;
    float* sb1 = (float*)(sWlo + 64 * SA);
    float* sw2 = sb1 + 64;

    const int tid = threadIdx.x;
    const bool isX = (blockIdx.y == 0);
    const float* __restrict__ src = isX ? X : Y;
    __half* __restrict__ dst = isX ? g_Xh : g_Yh;
    const int rowBase = blockIdx.x * 128;

    {
        const float4* w4 = (const float4*)W1;
        #pragma unroll
        for (int i = 0; i < 4; ++i) {
            int idx = tid + i * 256;
            int d = idx >> 4, kq = idx & 15;
            uint2 h, l;
            split4(w4[idx], h, l);
            *(uint2*)&sWhi[d * SA + kq * 4] = h;
            *(uint2*)&sWlo[d * SA + kq * 4] = l;
        }
    }
    {
        const float4* x4 = (const float4*)(src + (size_t)rowBase * 64);
        #pragma unroll
        for (int i = 0; i < 8; ++i) {
            int idx = tid + i * 256;
            int r = idx >> 4, kq = idx & 15;
            uint2 h, l;
            split4(x4[idx], h, l);
            *(uint2*)&sXhi[r * SA + kq * 4] = h;
            *(uint2*)&sXlo[r * SA + kq * 4] = l;
        }
    }
    if (tid < 64) { sb1[tid] = b1[tid]; sw2[tid] = w2[tid]; }
    __syncthreads();

    const int wid = tid >> 5, lane = tid & 31;
    const int wm = (wid >> 1) * 32;                  // 4 M groups of 32
    const int wn = (wid & 1) * 32;                   // 2 N groups of 32
    const int g = lane >> 2, tg2 = (lane & 3) * 2;

    // ldmatrix per-lane addresses (same verified formulas as stage2)
    const uint32_t aoff =
        (uint32_t)(wm + (lane & 7) + ((lane >> 3) & 1) * 8) * 144 +
        (uint32_t)((lane >> 4) * 8) * 2;
    const uint32_t uaAh = sb + aoff;
    const uint32_t uaAl = sb + S1_XLO + aoff;
    uint32_t uaBh[2], uaBl[2];
    #pragma unroll
    for (int p = 0; p < 2; ++p) {
        uint32_t boff =
            (uint32_t)(wn + p * 16 + (lane & 7) + ((lane >> 4) & 1) * 8) * 144 +
            (uint32_t)(((lane >> 3) & 1) * 8) * 2;
        uaBh[p] = sb + S1_WHI + boff;
        uaBl[p] = sb + S1_WLO + boff;
    }

    float acc[2][4][4];
    #pragma unroll
    for (int mi = 0; mi < 2; ++mi)
        #pragma unroll
        for (int ni = 0; ni < 4; ++ni)
            #pragma unroll
            for (int q = 0; q < 4; ++q) acc[mi][ni][q] = 0.0f;

    #pragma unroll
    for (int ks = 0; ks < 4; ++ks) {
        const uint32_t kb = (uint32_t)ks * 32;
        uint32_t a[2][4], bh[2][4], bl[2][4];
        ldm4(bh[0], uaBh[0] + kb);
        ldm4(bh[1], uaBh[1] + kb);
        ldm4(bl[0], uaBl[0] + kb);
        ldm4(bl[1], uaBl[1] + kb);
        ldm4(a[0], uaAh + kb);
        ldm4(a[1], uaAh + 2304u + kb);
        #pragma unroll
        for (int mi = 0; mi < 2; ++mi)
            #pragma unroll
            for (int ni = 0; ni < 4; ++ni) {
                mma_bf16(acc[mi][ni], a[mi], &bh[ni >> 1][(ni & 1) * 2]);
                mma_bf16(acc[mi][ni], a[mi], &bl[ni >> 1][(ni & 1) * 2]);
            }
        ldm4(a[0], uaAl + kb);
        ldm4(a[1], uaAl + 2304u + kb);
        #pragma unroll
        for (int mi = 0; mi < 2; ++mi)
            #pragma unroll
            for (int ni = 0; ni < 4; ++ni)
                mma_bf16(acc[mi][ni], a[mi], &bh[ni >> 1][(ni & 1) * 2]);
    }

    // ---- staged epilogue: frags -> shared [128] x 144B rows -> packed STG
    __syncthreads();                     // tiles dead; overlay buffer on sXhi
    #pragma unroll
    for (int mi = 0; mi < 2; ++mi) {
        #pragma unroll
        for (int ni = 0; ni < 4; ++ni) {
            const int col = wn + ni * 8 + tg2;
            float ba = sb1[col], bb = sb1[col + 1];
            float wa = sw2[col], wb = sw2[col + 1];
            const float* c = acc[mi][ni];
            #pragma unroll
            for (int half = 0; half < 2; ++half) {
                int row = wm + mi * 16 + half * 8 + g;
                float v0 = c[2 * half + 0] + ba;
                float v1 = c[2 * half + 1] + bb;
                if (isX) { v0 *= wa; v1 *= wb; }
                uint32_t v = pckh(__float2half_rn(v0), __float2half_rn(v1));
                asm volatile("st.shared.b32 [%0], %1;"
                             :: "r"(sb + (uint32_t)row * EP1_PITCH +
                                    (uint32_t)col * 2), "r"(v) : "memory");
            }
        }
    }
    __syncthreads();

    // each warp streams 16 full 128B rows (4 iters x 4 rows x 8 lanes x 16B)
    const int er = lane >> 3;            // 0..3
    const int ec = lane & 7;             // 0..7
    #pragma unroll
    for (int it = 0; it < 4; ++it) {
        int row = wid * 16 + it * 4 + er;
        uint4 v;
        asm volatile("ld.shared.v4.u32 {%0, %1, %2, %3}, [%4];"
                     : "=r"(v.x), "=r"(v.y), "=r"(v.z), "=r"(v.w)
                     : "r"(sb + (uint32_t)row * EP1_PITCH + (uint32_t)ec * 16));
        *(uint4*)(dst + (size_t)(rowBase + row) * 64 + ec * 8) = v;
    }
}

// ---------------------------------------------------------------------------
// Stage 2: pure fp16 HMMA GEMM, 64x128 CTA tile, smem-staged coalesced epi.
// (unchanged from R13 — best measured)
// ---------------------------------------------------------------------------
#define T_BH2 9216u
#define EPI_STRIDE 36
#define EPI_WBYTES 4608u        // 32*36*4
#define S2_SMEM 36864

__global__ __launch_bounds__(256, 3) void stage2_mma(
    const float* __restrict__ b2p, float* __restrict__ out)
{
    extern __shared__ __half sm2[];
    const uint32_t sb = smem_u32(sm2);

    const int tid  = threadIdx.x;
    const int bhz  = blockIdx.z;
    const int mBase = blockIdx.y * 64;
    const int nBase = blockIdx.x * 128;

    // ---- async fills: A (64x64) + B (128x64)
    {
        const uint4* aH = (const uint4*)(g_Xh + (size_t)(bhz * Lq + mBase) * 64);
        #pragma unroll
        for (int i = 0; i < 2; ++i) {
            int idx = tid + i * 256;                 // 512 x 16B chunks
            int row = idx >> 3, c = idx & 7;
            CP16(sb + (uint32_t)row * 144 + (uint32_t)c * 16, aH + idx);
        }
        const uint4* bH = (const uint4*)(g_Yh + (size_t)(bhz * Lq + nBase) * 64);
        #pragma unroll
        for (int i = 0; i < 4; ++i) {
            int idx = tid + i * 256;                 // 1024 x 16B chunks
            int row = idx >> 3, c = idx & 7;
            CP16(sb + T_BH2 + (uint32_t)row * 144 + (uint32_t)c * 16, bH + idx);
        }
        CP_COMMIT();
    }

    // ---- per-lane ldmatrix addresses (while loads fly)
    const int wid = tid >> 5, lane = tid & 31;
    const int wm = (wid >> 2) * 32;                  // 2 M groups of 32
    const int wn = (wid & 3) * 32;                   // 4 N groups of 32
    const int g = lane >> 2, tg2 = (lane & 3) * 2;

    const uint32_t aoff =
        (uint32_t)(wm + (lane & 7) + ((lane >> 3) & 1) * 8) * 144 +
        (uint32_t)((lane >> 4) * 8) * 2;
    const uint32_t uaA = sb + aoff;
    uint32_t uaB[2];
    #pragma unroll
    for (int p = 0; p < 2; ++p) {
        uint32_t boff =
            (uint32_t)(wn + p * 16 + (lane & 7) + ((lane >> 4) & 1) * 8) * 144 +
            (uint32_t)(((lane >> 3) & 1) * 8) * 2;
        uaB[p] = sb + T_BH2 + boff;
    }
    const float b2 = __ldg(b2p);

    float acc[2][4][4];
    #pragma unroll
    for (int mi = 0; mi < 2; ++mi)
        #pragma unroll
        for (int ni = 0; ni < 4; ++ni)
            #pragma unroll
            for (int q = 0; q < 4; ++q) acc[mi][ni][q] = 0.0f;

    CP_WAIT0();
    __syncthreads();

    #pragma unroll
    for (int ks = 0; ks < 4; ++ks) {
        const uint32_t kb = (uint32_t)ks * 32;       // 16 halves = 32 B
        uint32_t a[2][4], bf[2][4];
        ldm4(bf[0], uaB[0] + kb);
        ldm4(bf[1], uaB[1] + kb);
        ldm4(a[0], uaA + kb);
        ldm4(a[1], uaA + 2304u + kb);
        #pragma unroll
        for (int mi = 0; mi < 2; ++mi)
            #pragma unroll
            for (int ni = 0; ni < 4; ++ni)
                mma_f16(acc[mi][ni], a[mi], &bf[ni >> 1][(ni & 1) * 2]);
    }

    // ---- epilogue: bias+relu in regs -> per-warp smem tile -> coalesced STG
    __syncthreads();                 // tiles dead; safe to overlay epi buffers
    const uint32_t ebuf = sb + (uint32_t)wid * EPI_WBYTES;

    #pragma unroll
    for (int mi = 0; mi < 2; ++mi) {
        #pragma unroll
        for (int ni = 0; ni < 4; ++ni) {
            #pragma unroll
            for (int half = 0; half < 2; ++half) {
                int row = mi * 16 + half * 8 + g;
                int col = ni * 8 + tg2;
                float2 v;
                v.x = fmaxf(acc[mi][ni][2 * half + 0] + b2, 0.0f);
                v.y = fmaxf(acc[mi][ni][2 * half + 1] + b2, 0.0f);
                asm volatile("st.shared.v2.f32 [%0], {%1, %2};"
                             :: "r"(ebuf + (uint32_t)(row * EPI_STRIDE + col) * 4),
                                "f"(v.x), "f"(v.y) : "memory");
            }
        }
    }
    __syncwarp();

    // each warp streams its own 32x32 tile: 8 iters x (4 rows x 8 lanes x 16B)
    const int er = lane >> 3;            // 0..3
    const int ec = (lane & 7) * 4;       // 0,4,...,28
    float* gout = out + ((size_t)bhz * Lq + mBase + wm) * Lq + nBase + wn;
    #pragma unroll
    for (int it = 0; it < 8; ++it) {
        int row = it * 4 + er;
        float4 v;
        asm volatile("ld.shared.v4.f32 {%0, %1, %2, %3}, [%4];"
                     : "=f"(v.x), "=f"(v.y), "=f"(v.z), "=f"(v.w)
                     : "r"(ebuf + (uint32_t)(row * EPI_STRIDE + ec) * 4));
        *(float4*)(gout + (size_t)row * Lq + ec) = v;
    }
}

// ---------------------------------------------------------------------------
extern "C" void kernel_launch(void* const* d_in, const int* in_sizes, int n_in,
                              void* d_out, int out_size)
{
    const float* X  = (const float*)d_in[0];
    const float* Y  = (const float*)d_in[1];
    const float* W1 = (const float*)d_in[2];
    const float* b1 = (const float*)d_in[3];
    const float* w2 = (const float*)d_in[4];
    const float* b2 = (const float*)d_in[5];
    float* out = (float*)d_out;

    const int s1_smem = (2 * 128 * SA + 2 * 64 * SA) * 2 + 2 * 64 * 4;  // 55808
    cudaFuncSetAttribute(stage1_kernel,
                         cudaFuncAttributeMaxDynamicSharedMemorySize, s1_smem);
    stage1_kernel<<<dim3(BH * Lq / 128, 2, 1), 256, s1_smem>>>(X, Y, W1, b1, w2);

    cudaFuncSetAttribute(stage2_mma,
                         cudaFuncAttributeMaxDynamicSharedMemorySize, S2_SMEM);
    stage2_mma<<<dim3(8, 16, BH), 256, S2_SMEM>>>(b2, out);
}

// round 17
// speedup vs baseline: 1.4508x; 1.1430x over previous
#include <cuda_runtime.h>
#include <cuda_bf16.h>
#include <cuda_fp16.h>
#include <cstdint>

#define BH 32
#define Lq 1024
#define Dd 64

// Scratch: fp16 projected activations.
__device__ __half g_Xh[BH * Lq * Dd];
__device__ __half g_Yh[BH * Lq * Dd];

// ======================== helpers ===========================
__device__ __forceinline__ uint32_t smem_u32(const void* p) {
    uint32_t a;
    asm("{ .reg .u64 t; cvta.to.shared.u64 t, %1; cvt.u32.u64 %0, t; }"
        : "=r"(a) : "l"(p));
    return a;
}
#define CP16(dst, src) \
    asm volatile("cp.async.cg.shared.global [%0], [%1], 16;" :: "r"(dst), "l"(src) : "memory")
#define CP_COMMIT() asm volatile("cp.async.commit_group;" ::: "memory")
#define CP_WAIT(n)  asm volatile("cp.async.wait_group %0;" :: "n"(n) : "memory")

__device__ __forceinline__ void ldm4(uint32_t* r, uint32_t addr) {
    asm volatile("ldmatrix.sync.aligned.m8n8.x4.shared.b16 {%0,%1,%2,%3}, [%4];"
                 : "=r"(r[0]), "=r"(r[1]), "=r"(r[2]), "=r"(r[3]) : "r"(addr));
}
__device__ __forceinline__ void mma_bf16(float* c, const uint32_t* a, const uint32_t* b) {
    asm volatile(
        "mma.sync.aligned.m16n8k16.row.col.f32.bf16.bf16.f32 "
        "{%0,%1,%2,%3}, {%4,%5,%6,%7}, {%8,%9}, {%0,%1,%2,%3};"
        : "+f"(c[0]), "+f"(c[1]), "+f"(c[2]), "+f"(c[3])
        : "r"(a[0]), "r"(a[1]), "r"(a[2]), "r"(a[3]), "r"(b[0]), "r"(b[1]));
}
__device__ __forceinline__ void mma_f16(float* c, const uint32_t* a, const uint32_t* b) {
    asm volatile(
        "mma.sync.aligned.m16n8k16.row.col.f32.f16.f16.f32 "
        "{%0,%1,%2,%3}, {%4,%5,%6,%7}, {%8,%9}, {%0,%1,%2,%3};"
        : "+f"(c[0]), "+f"(c[1]), "+f"(c[2]), "+f"(c[3])
        : "r"(a[0]), "r"(a[1]), "r"(a[2]), "r"(a[3]), "r"(b[0]), "r"(b[1]));
}
__device__ __forceinline__ uint32_t pck(__nv_bfloat16 a, __nv_bfloat16 b) {
    __nv_bfloat162 t; t.x = a; t.y = b;
    return *(uint32_t*)&t;
}
__device__ __forceinline__ uint32_t pckh(__half a, __half b) {
    __half2 t; t.x = a; t.y = b;
    return *(uint32_t*)&t;
}
__device__ __forceinline__ void split4(float4 v, uint2& h, uint2& l) {
    __nv_bfloat16 h0 = __float2bfloat16(v.x), h1 = __float2bfloat16(v.y);
    __nv_bfloat16 h2 = __float2bfloat16(v.z), h3 = __float2bfloat16(v.w);
    __nv_bfloat16 l0 = __float2bfloat16(v.x - __bfloat162float(h0));
    __nv_bfloat16 l1 = __float2bfloat16(v.y - __bfloat162float(h1));
    __nv_bfloat16 l2 = __float2bfloat16(v.z - __bfloat162float(h2));
    __nv_bfloat16 l3 = __float2bfloat16(v.w - __bfloat162float(h3));
    h.x = pck(h0, h1); h.y = pck(h2, h3);
    l.x = pck(l0, l1); l.y = pck(l2, l3);
}

#define SA 72   // 16-bit tile stride (144 B rows)

// ---------------------------------------------------------------------------
// Stage 1: projection as bf16 3-term HMMA GEMM. 64-row CTAs for balance.
// grid = (512, 2); block = 256; smem 37376 B.
// Layout: sXhi@0(9216) sXlo@9216 sWhi@18432 sWlo@27648 sb1@36864 sw2@37120
// Epilogue buffer overlays sXhi: 64 rows x 144 B pitch.
// ---------------------------------------------------------------------------
#define S1_XLO 9216u
#define S1_WHI 18432u
#define S1_WLO 27648u
#define S1_SMEM 37376

__global__ __launch_bounds__(256) void stage1_kernel(
    const float* __restrict__ X, const float* __restrict__ Y,
    const float* __restrict__ W1, const float* __restrict__ b1,
    const float* __restrict__ w2)
{
    extern __shared__ __nv_bfloat16 s1[];
    const uint32_t sb = smem_u32(s1);
    __nv_bfloat16* sXhi = s1;
    __nv_bfloat16* sXlo = s1 + 64 * SA;
    __nv_bfloat16* sWhi = s1 + 2 * 64 * SA;
    __nv_bfloat16* sWlo = s1 + 3 * 64 * SA;
    float* sb1 = (float*)(s1 + 4 * 64 * SA);
    float* sw2 = sb1 + 64;

    const int tid = threadIdx.x;
    const bool isX = (blockIdx.y == 0);
    const float* __restrict__ src = isX ? X : Y;
    __half* __restrict__ dst = isX ? g_Xh : g_Yh;
    const int rowBase = blockIdx.x * 64;

    // W1 [64][64] -> hi/lo smem (4 float4 / thread)
    {
        const float4* w4 = (const float4*)W1;
        #pragma unroll
        for (int i = 0; i < 4; ++i) {
            int idx = tid + i * 256;
            int d = idx >> 4, kq = idx & 15;
            uint2 h, l;
            split4(w4[idx], h, l);
            *(uint2*)&sWhi[d * SA + kq * 4] = h;
            *(uint2*)&sWlo[d * SA + kq * 4] = l;
        }
    }
    // X tile [64][64] -> hi/lo smem (4 float4 / thread)
    {
        const float4* x4 = (const float4*)(src + (size_t)rowBase * 64);
        #pragma unroll
        for (int i = 0; i < 4; ++i) {
            int idx = tid + i * 256;
            int r = idx >> 4, kq = idx & 15;
            uint2 h, l;
            split4(x4[idx], h, l);
            *(uint2*)&sXhi[r * SA + kq * 4] = h;
            *(uint2*)&sXlo[r * SA + kq * 4] = l;
        }
    }
    if (tid < 64) { sb1[tid] = b1[tid]; sw2[tid] = w2[tid]; }
    __syncthreads();

    const int wid = tid >> 5, lane = tid & 31;
    const int wm = (wid >> 1) * 16;                  // 4 M groups of 16
    const int wn = (wid & 1) * 32;                   // 2 N groups of 32
    const int g = lane >> 2, tg2 = (lane & 3) * 2;

    const uint32_t aoff =
        (uint32_t)(wm + (lane & 7) + ((lane >> 3) & 1) * 8) * 144 +
        (uint32_t)((lane >> 4) * 8) * 2;
    const uint32_t uaAh = sb + aoff;
    const uint32_t uaAl = sb + S1_XLO + aoff;
    uint32_t uaBh[2], uaBl[2];
    #pragma unroll
    for (int p = 0; p < 2; ++p) {
        uint32_t boff =
            (uint32_t)(wn + p * 16 + (lane & 7) + ((lane >> 4) & 1) * 8) * 144 +
            (uint32_t)(((lane >> 3) & 1) * 8) * 2;
        uaBh[p] = sb + S1_WHI + boff;
        uaBl[p] = sb + S1_WLO + boff;
    }

    float acc[4][4];
    #pragma unroll
    for (int ni = 0; ni < 4; ++ni)
        #pragma unroll
        for (int q = 0; q < 4; ++q) acc[ni][q] = 0.0f;

    #pragma unroll
    for (int ks = 0; ks < 4; ++ks) {
        const uint32_t kb = (uint32_t)ks * 32;
        uint32_t a[4], bh[2][4], bl[2][4];
        ldm4(bh[0], uaBh[0] + kb);
        ldm4(bh[1], uaBh[1] + kb);
        ldm4(bl[0], uaBl[0] + kb);
        ldm4(bl[1], uaBl[1] + kb);
        ldm4(a, uaAh + kb);
        #pragma unroll
        for (int ni = 0; ni < 4; ++ni) {
            mma_bf16(acc[ni], a, &bh[ni >> 1][(ni & 1) * 2]);
            mma_bf16(acc[ni], a, &bl[ni >> 1][(ni & 1) * 2]);
        }
        ldm4(a, uaAl + kb);
        #pragma unroll
        for (int ni = 0; ni < 4; ++ni)
            mma_bf16(acc[ni], a, &bh[ni >> 1][(ni & 1) * 2]);
    }

    // ---- staged epilogue: frags -> shared 64 x 144B rows -> packed STG
    __syncthreads();                     // tiles dead; overlay buffer on sXhi
    #pragma unroll
    for (int ni = 0; ni < 4; ++ni) {
        const int col = wn + ni * 8 + tg2;
        float ba = sb1[col], bb = sb1[col + 1];
        float wa = sw2[col], wb = sw2[col + 1];
        #pragma unroll
        for (int half = 0; half < 2; ++half) {
            int row = wm + half * 8 + g;
            float v0 = acc[ni][2 * half + 0] + ba;
            float v1 = acc[ni][2 * half + 1] + bb;
            if (isX) { v0 *= wa; v1 *= wb; }
            uint32_t v = pckh(__float2half_rn(v0), __float2half_rn(v1));
            asm volatile("st.shared.b32 [%0], %1;"
                         :: "r"(sb + (uint32_t)row * 144 + (uint32_t)col * 2),
                            "r"(v) : "memory");
        }
    }
    __syncthreads();

    // each warp streams 8 full 128B rows (2 iters x 4 rows x 8 lanes x 16B)
    const int er = lane >> 3;            // 0..3
    const int ec = lane & 7;             // 0..7
    #pragma unroll
    for (int it = 0; it < 2; ++it) {
        int row = wid * 8 + it * 4 + er;
        uint4 v;
        asm volatile("ld.shared.v4.u32 {%0, %1, %2, %3}, [%4];"
                     : "=r"(v.x), "=r"(v.y), "=r"(v.z), "=r"(v.w)
                     : "r"(sb + (uint32_t)row * 144 + (uint32_t)ec * 16));
        *(uint4*)(dst + (size_t)(rowBase + row) * 64 + ec * 8) = v;
    }
}

// ---------------------------------------------------------------------------
// Stage 2: fp16 1-term HMMA, 64x256 strip per CTA, B double-buffered.
// grid = (4, 16, 32) = 2048, block = 256 (8 warps, 32x32 warp tile/tile).
// smem 46080 B: A@0 [64][72] | B0@9216 [128][72] | B1@27648 [128][72]
// Epilogue: per-warp 16-row chunks (2304 B x 8 = 18432) overlay B0 ONLY.
// ---------------------------------------------------------------------------
#define T2_B0 9216u
#define T2_B1 27648u
#define EPW   2304u             // 16 rows x 144 B per-warp epi chunk
#define S2_SMEM 46080

__global__ __launch_bounds__(256, 3) void stage2_mma(
    const float* __restrict__ b2p, float* __restrict__ out)
{
    extern __shared__ __half sm2[];
    const uint32_t sb = smem_u32(sm2);

    const int tid  = threadIdx.x;
    const int bhz  = blockIdx.z;
    const int mBase = blockIdx.y * 64;
    const int nBase = blockIdx.x * 256;

    // ---- async fills: A (64x64) + B0 (128x64); then B1 prefetch
    {
        const uint4* aH = (const uint4*)(g_Xh + (size_t)(bhz * Lq + mBase) * 64);
        #pragma unroll
        for (int i = 0; i < 2; ++i) {
            int idx = tid + i * 256;
            int row = idx >> 3, c = idx & 7;
            CP16(sb + (uint32_t)row * 144 + (uint32_t)c * 16, aH + idx);
        }
        const uint4* b0 = (const uint4*)(g_Yh + (size_t)(bhz * Lq + nBase) * 64);
        #pragma unroll
        for (int i = 0; i < 4; ++i) {
            int idx = tid + i * 256;
            int row = idx >> 3, c = idx & 7;
            CP16(sb + T2_B0 + (uint32_t)row * 144 + (uint32_t)c * 16, b0 + idx);
        }
        CP_COMMIT();
        const uint4* b1 = (const uint4*)(g_Yh + (size_t)(bhz * Lq + nBase + 128) * 64);
        #pragma unroll
        for (int i = 0; i < 4; ++i) {
            int idx = tid + i * 256;
            int row = idx >> 3, c = idx & 7;
            CP16(sb + T2_B1 + (uint32_t)row * 144 + (uint32_t)c * 16, b1 + idx);
        }
        CP_COMMIT();
    }

    const int wid = tid >> 5, lane = tid & 31;
    const int wm = (wid >> 2) * 32;                  // 2 M groups of 32
    const int wn = (wid & 3) * 32;                   // 4 N groups of 32
    const int g = lane >> 2, tg2 = (lane & 3) * 2;

    const uint32_t aoff =
        (uint32_t)(wm + (lane & 7) + ((lane >> 3) & 1) * 8) * 144 +
        (uint32_t)((lane >> 4) * 8) * 2;
    const uint32_t uaA = sb + aoff;
    uint32_t boff[2];
    #pragma unroll
    for (int p = 0; p < 2; ++p)
        boff[p] =
            (uint32_t)(wn + p * 16 + (lane & 7) + ((lane >> 4) & 1) * 8) * 144 +
            (uint32_t)(((lane >> 3) & 1) * 8) * 2;
    const float b2 = __ldg(b2p);

    const uint32_t ebuf = sb + T2_B0 + (uint32_t)wid * EPW;
    const int er = lane >> 3;            // 0..3
    const int ec = (lane & 7) * 4;       // 0,4,...,28

    CP_WAIT(1);                          // A + B0 resident
    __syncthreads();

    #pragma unroll
    for (int bt = 0; bt < 2; ++bt) {
        const uint32_t bbase = sb + (bt == 0 ? T2_B0 : T2_B1);

        float acc[2][4][4];
        #pragma unroll
        for (int mi = 0; mi < 2; ++mi)
            #pragma unroll
            for (int ni = 0; ni < 4; ++ni)
                #pragma unroll
                for (int q = 0; q < 4; ++q) acc[mi][ni][q] = 0.0f;

        #pragma unroll
        for (int ks = 0; ks < 4; ++ks) {
            const uint32_t kb = (uint32_t)ks * 32;
            uint32_t a[2][4], bf[2][4];
            ldm4(bf[0], bbase + boff[0] + kb);
            ldm4(bf[1], bbase + boff[1] + kb);
            ldm4(a[0], uaA + kb);
            ldm4(a[1], uaA + 2304u + kb);
            #pragma unroll
            for (int mi = 0; mi < 2; ++mi)
                #pragma unroll
                for (int ni = 0; ni < 4; ++ni)
                    mma_f16(acc[mi][ni], a[mi], &bf[ni >> 1][(ni & 1) * 2]);
        }

        if (bt == 0) {
            CP_WAIT(0);                  // B1 arrived
            __syncthreads();             // all warps done reading B0
        }

        // ---- epilogue: 2 chunks of 16 rows through per-warp B0-region buffer
        float* gtile = out + ((size_t)bhz * Lq + mBase + wm) * Lq +
                       nBase + bt * 128 + wn;
        #pragma unroll
        for (int mi = 0; mi < 2; ++mi) {
            #pragma unroll
            for (int ni = 0; ni < 4; ++ni) {
                #pragma unroll
                for (int half = 0; half < 2; ++half) {
                    int row = half * 8 + g;          // 0..15 within chunk
                    int col = ni * 8 + tg2;
                    float2 v;
                    v.x = fmaxf(acc[mi][ni][2 * half + 0] + b2, 0.0f);
                    v.y = fmaxf(acc[mi][ni][2 * half + 1] + b2, 0.0f);
                    asm volatile("st.shared.v2.f32 [%0], {%1, %2};"
                                 :: "r"(ebuf + (uint32_t)(row * 36 + col) * 4),
                                    "f"(v.x), "f"(v.y) : "memory");
                }
            }
            __syncwarp();
            #pragma unroll
            for (int it = 0; it < 4; ++it) {
                int row = it * 4 + er;               // 0..15 within chunk
                float4 v;
                asm volatile("ld.shared.v4.f32 {%0, %1, %2, %3}, [%4];"
                             : "=f"(v.x), "=f"(v.y), "=f"(v.z), "=f"(v.w)
                             : "r"(ebuf + (uint32_t)(row * 36 + ec) * 4));
                *(float4*)(gtile + (size_t)(mi * 16 + row) * Lq + ec) = v;
            }
            __syncwarp();                // buffer reuse for next chunk
        }
    }
}

// ---------------------------------------------------------------------------
extern "C" void kernel_launch(void* const* d_in, const int* in_sizes, int n_in,
                              void* d_out, int out_size)
{
    const float* X  = (const float*)d_in[0];
    const float* Y  = (const float*)d_in[1];
    const float* W1 = (const float*)d_in[2];
    const float* b1 = (const float*)d_in[3];
    const float* w2 = (const float*)d_in[4];
    const float* b2 = (const float*)d_in[5];
    float* out = (float*)d_out;

    cudaFuncSetAttribute(stage1_kernel,
                         cudaFuncAttributeMaxDynamicSharedMemorySize, S1_SMEM);
    stage1_kernel<<<dim3(BH * Lq / 64, 2, 1), 256, S1_SMEM>>>(X, Y, W1, b1, w2);

    cudaFuncSetAttribute(stage2_mma,
                         cudaFuncAttributeMaxDynamicSharedMemorySize, S2_SMEM);
    stage2_mma<<<dim3(4, 16, BH), 256, S2_SMEM>>>(b2, out);
}